// round 9
// baseline (speedup 1.0000x reference)
#include <cuda_runtime.h>
#include <cuda_bf16.h>
#include <cstdint>

#define NTOK  32768
#define DIMD  256
#define HEADS 8
#define MSAH  128
#define MSAW  256
#define PLD   3072   // P cols: [wq(512) | wk@512 | wv@1024 | hq@1536 | hk@2048 | hv@2560]
#define OLD   1024   // O cols: [Ow(512) | Oh(512)]
#define TSC   0.011048543456039806f  // 64^-0.5 * 128^-0.5

// ---------------------------------------------------------------------------
// Scratch
// ---------------------------------------------------------------------------
__device__ __nv_bfloat16 g_Ph[(size_t)NTOK * PLD];
__device__ __nv_bfloat16 g_Pl[(size_t)NTOK * PLD];
__device__ float g_Shp[4 * HEADS * 256 * 256];
__device__ __nv_bfloat16 g_Shh[HEADS * 256 * 256];
__device__ __nv_bfloat16 g_Shl[HEADS * 256 * 256];
__device__ __nv_bfloat16 g_xh[(size_t)NTOK * DIMD];
__device__ __nv_bfloat16 g_xl[(size_t)NTOK * DIMD];
__device__ __nv_bfloat16 g_Bph[3072 * 256];
__device__ __nv_bfloat16 g_Bpl[3072 * 256];
__device__ __nv_bfloat16 g_Ohi[(size_t)NTOK * OLD];
__device__ __nv_bfloat16 g_Olo[(size_t)NTOK * OLD];
__device__ __nv_bfloat16 g_Boh[256 * 1024];
__device__ __nv_bfloat16 g_Bol[256 * 1024];

// ---------------------------------------------------------------------------
// PTX helpers (compute_103-safe)
// ---------------------------------------------------------------------------
__device__ __forceinline__ uint32_t smem_to_u32(const void* p) {
    uint32_t a;
    asm("{ .reg .u64 t; cvta.to.shared.u64 t, %1; cvt.u32.u64 %0, t; }" : "=r"(a) : "l"(p));
    return a;
}
#define CP_ASYNC16(dst, src) \
    asm volatile("cp.async.cg.shared.global [%0], [%1], 16;" :: "r"(dst), "l"(src) : "memory")
#define CP_COMMIT() asm volatile("cp.async.commit_group;" ::: "memory")
#define CP_WAIT0()  asm volatile("cp.async.wait_group 0;" ::: "memory")
#define CP_WAIT1()  asm volatile("cp.async.wait_group 1;" ::: "memory")

#define LDMATRIX_X4(d0, d1, d2, d3, addr) \
    asm volatile("ldmatrix.sync.aligned.m8n8.x4.shared.b16 {%0,%1,%2,%3}, [%4];" \
        : "=r"(d0), "=r"(d1), "=r"(d2), "=r"(d3) : "r"(addr))
#define LDMATRIX_X4_T(d0, d1, d2, d3, addr) \
    asm volatile("ldmatrix.sync.aligned.m8n8.x4.trans.shared.b16 {%0,%1,%2,%3}, [%4];" \
        : "=r"(d0), "=r"(d1), "=r"(d2), "=r"(d3) : "r"(addr))

#define MMA_BF16(c, a0, a1, a2, a3, b0, b1) \
    asm volatile("mma.sync.aligned.m16n8k16.row.col.f32.bf16.bf16.f32 " \
        "{%0,%1,%2,%3}, {%4,%5,%6,%7}, {%8,%9}, {%0,%1,%2,%3};" \
        : "+f"((c)[0]), "+f"((c)[1]), "+f"((c)[2]), "+f"((c)[3]) \
        : "r"(a0), "r"(a1), "r"(a2), "r"(a3), "r"(b0), "r"(b1))

__device__ __forceinline__ uint32_t pack_bf16x2(float lo, float hi) {
    __nv_bfloat162 t = __floats2bfloat162_rn(lo, hi);
    return *reinterpret_cast<uint32_t*>(&t);
}
__device__ __forceinline__ void split2_store(__nv_bfloat16* hi, __nv_bfloat16* lo,
                                             float a, float b) {
    __nv_bfloat16 ha = __float2bfloat16(a), hb = __float2bfloat16(b);
    __nv_bfloat162 h; h.x = ha; h.y = hb;
    *reinterpret_cast<__nv_bfloat162*>(hi) = h;
    __nv_bfloat162 l;
    l.x = __float2bfloat16(a - __bfloat162float(ha));
    l.y = __float2bfloat16(b - __bfloat162float(hb));
    *reinterpret_cast<__nv_bfloat162*>(lo) = l;
}

// ---------------------------------------------------------------------------
// 128x128 tile compute (used by dots_h): one 32-k chunk, warp tile 32x64.
// ---------------------------------------------------------------------------
__device__ __forceinline__ void compute_chunk128(uint32_t sAst, uint32_t sBst,
                                                 int lane, int wm, int wn,
                                                 float acc[2][8][4])
{
#pragma unroll
    for (int kb = 0; kb < 2; kb++) {
        const int lg = kb * 2 + (lane >> 4);
        uint32_t ah[2][4], al[2][4];
#pragma unroll
        for (int mi = 0; mi < 2; mi++) {
            const int row = wm * 32 + mi * 16 + (lane & 15);
            LDMATRIX_X4(ah[mi][0], ah[mi][1], ah[mi][2], ah[mi][3],
                        sAst + row * 128 + (((lg) ^ (row & 7)) << 4));
            LDMATRIX_X4(al[mi][0], al[mi][1], al[mi][2], al[mi][3],
                        sAst + row * 128 + (((lg + 4) ^ (row & 7)) << 4));
        }
        uint32_t b[4][4];
#pragma unroll
        for (int nf = 0; nf < 4; nf++) {
            const int row = wn * 64 + nf * 16 + (lane & 15);
            LDMATRIX_X4(b[nf][0], b[nf][1], b[nf][2], b[nf][3],
                        sBst + row * 128 + (((lg) ^ (row & 7)) << 4));
        }
#pragma unroll
        for (int nf = 0; nf < 4; nf++)
#pragma unroll
            for (int mi = 0; mi < 2; mi++) {
                MMA_BF16(acc[mi][2 * nf],     ah[mi][0], ah[mi][1], ah[mi][2], ah[mi][3], b[nf][0], b[nf][2]);
                MMA_BF16(acc[mi][2 * nf + 1], ah[mi][0], ah[mi][1], ah[mi][2], ah[mi][3], b[nf][1], b[nf][3]);
            }
#pragma unroll
        for (int nf = 0; nf < 4; nf++)
#pragma unroll
            for (int mi = 0; mi < 2; mi++) {
                MMA_BF16(acc[mi][2 * nf],     al[mi][0], al[mi][1], al[mi][2], al[mi][3], b[nf][0], b[nf][2]);
                MMA_BF16(acc[mi][2 * nf + 1], al[mi][0], al[mi][1], al[mi][2], al[mi][3], b[nf][1], b[nf][3]);
            }
#pragma unroll
        for (int nf = 0; nf < 4; nf++) {
            const int row = wn * 64 + nf * 16 + (lane & 15);
            LDMATRIX_X4(b[nf][0], b[nf][1], b[nf][2], b[nf][3],
                        sBst + row * 128 + (((lg + 4) ^ (row & 7)) << 4));
        }
#pragma unroll
        for (int nf = 0; nf < 4; nf++)
#pragma unroll
            for (int mi = 0; mi < 2; mi++) {
                MMA_BF16(acc[mi][2 * nf],     ah[mi][0], ah[mi][1], ah[mi][2], ah[mi][3], b[nf][0], b[nf][2]);
                MMA_BF16(acc[mi][2 * nf + 1], ah[mi][0], ah[mi][1], ah[mi][2], ah[mi][3], b[nf][1], b[nf][3]);
            }
    }
}

// ---------------------------------------------------------------------------
// Fused hi/lo split-bf16 GEMM. Tile 128(M)x64(N), warp tile 32x32, acc=32
// regs/thread -> 3 CTAs/SM (24 warps) for latency hiding.
// Stage = A 16KB + B 8KB = 24KB; 3 stages = 72KB; x3 CTAs = 216KB <= 228.
// ---------------------------------------------------------------------------
#define GEMM_SMEM (3 * 24576)

__global__ __launch_bounds__(256, 3)
void gemm_mma(const __nv_bfloat16* __restrict__ Ah, const __nv_bfloat16* __restrict__ Al, int lda,
              const __nv_bfloat16* __restrict__ Bh, const __nv_bfloat16* __restrict__ Bl, int ldb,
              float* __restrict__ C,
              __nv_bfloat16* __restrict__ Chi, __nv_bfloat16* __restrict__ Clo,
              int ldc, int K,
              const float* __restrict__ bias1, const float* __restrict__ bias2)
{
    extern __shared__ char smem[];
    const uint32_t sb = smem_to_u32(smem);
    const int tid = threadIdx.x, lane = tid & 31, wid = tid >> 5;
    const int wm = wid & 3, wn = wid >> 2;        // warp grid 4(m) x 2(n)
    const int m0 = blockIdx.y * 128, j0 = blockIdx.x * 64;
    const int NC = K >> 5;

    float acc[2][4][4];
#pragma unroll
    for (int i = 0; i < 2; i++)
#pragma unroll
        for (int j = 0; j < 4; j++)
#pragma unroll
            for (int u = 0; u < 4; u++) acc[i][j][u] = 0.f;

    auto load_chunk = [&](int c, int s) {
        const int kc = c << 5;
        const uint32_t sA = sb + s * 24576, sB = sA + 16384;
        // A: 128 rows x 8 granules = 1024 slots
#pragma unroll
        for (int i = 0; i < 4; i++) {
            const int id = tid + i * 256;
            const int row = id & 127, g = id >> 7;
            const uint32_t off = row * 128 + ((g ^ (row & 7)) << 4);
            const __nv_bfloat16* Asrc = (g < 4) ? Ah : Al;
            CP_ASYNC16(sA + off, Asrc + (size_t)(m0 + row) * lda + kc + (g & 3) * 8);
        }
        // B: 64 rows x 8 granules = 512 slots
#pragma unroll
        for (int i = 0; i < 2; i++) {
            const int id = tid + i * 256;
            const int row = id & 63, g = id >> 6;
            const uint32_t off = row * 128 + ((g ^ (row & 7)) << 4);
            const __nv_bfloat16* Bsrc = (g < 4) ? Bh : Bl;
            CP_ASYNC16(sB + off, Bsrc + (size_t)(j0 + row) * ldb + kc + (g & 3) * 8);
        }
        CP_COMMIT();
    };

    load_chunk(0, 0);
    load_chunk(1, 1);
    for (int c = 0; c < NC; c++) {
        if (c < NC - 1) { CP_WAIT1(); } else { CP_WAIT0(); }
        __syncthreads();
        if (c + 2 < NC) load_chunk(c + 2, (c + 2) % 3);
        const uint32_t sA = sb + (c % 3) * 24576, sB = sA + 16384;
#pragma unroll
        for (int kb = 0; kb < 2; kb++) {
            const int lg = kb * 2 + (lane >> 4);
            uint32_t ah[2][4], al[2][4];
#pragma unroll
            for (int mi = 0; mi < 2; mi++) {
                const int row = wm * 32 + mi * 16 + (lane & 15);
                LDMATRIX_X4(ah[mi][0], ah[mi][1], ah[mi][2], ah[mi][3],
                            sA + row * 128 + (((lg) ^ (row & 7)) << 4));
                LDMATRIX_X4(al[mi][0], al[mi][1], al[mi][2], al[mi][3],
                            sA + row * 128 + (((lg + 4) ^ (row & 7)) << 4));
            }
            uint32_t b[2][4];
#pragma unroll
            for (int nf = 0; nf < 2; nf++) {
                const int row = wn * 32 + nf * 16 + (lane & 15);
                LDMATRIX_X4(b[nf][0], b[nf][1], b[nf][2], b[nf][3],
                            sB + row * 128 + (((lg) ^ (row & 7)) << 4));
            }
#pragma unroll
            for (int nf = 0; nf < 2; nf++)
#pragma unroll
                for (int mi = 0; mi < 2; mi++) {
                    MMA_BF16(acc[mi][2 * nf],     ah[mi][0], ah[mi][1], ah[mi][2], ah[mi][3], b[nf][0], b[nf][2]);
                    MMA_BF16(acc[mi][2 * nf + 1], ah[mi][0], ah[mi][1], ah[mi][2], ah[mi][3], b[nf][1], b[nf][3]);
                }
#pragma unroll
            for (int nf = 0; nf < 2; nf++)
#pragma unroll
                for (int mi = 0; mi < 2; mi++) {
                    MMA_BF16(acc[mi][2 * nf],     al[mi][0], al[mi][1], al[mi][2], al[mi][3], b[nf][0], b[nf][2]);
                    MMA_BF16(acc[mi][2 * nf + 1], al[mi][0], al[mi][1], al[mi][2], al[mi][3], b[nf][1], b[nf][3]);
                }
#pragma unroll
            for (int nf = 0; nf < 2; nf++) {
                const int row = wn * 32 + nf * 16 + (lane & 15);
                LDMATRIX_X4(b[nf][0], b[nf][1], b[nf][2], b[nf][3],
                            sB + row * 128 + (((lg + 4) ^ (row & 7)) << 4));
            }
#pragma unroll
            for (int nf = 0; nf < 2; nf++)
#pragma unroll
                for (int mi = 0; mi < 2; mi++) {
                    MMA_BF16(acc[mi][2 * nf],     ah[mi][0], ah[mi][1], ah[mi][2], ah[mi][3], b[nf][0], b[nf][2]);
                    MMA_BF16(acc[mi][2 * nf + 1], ah[mi][0], ah[mi][1], ah[mi][2], ah[mi][3], b[nf][1], b[nf][3]);
                }
        }
    }

    const int qrow = lane >> 2, qcol2 = (lane & 3) * 2;
    if (C) {
#pragma unroll
        for (int nj = 0; nj < 4; nj++) {
            const int n = j0 + wn * 32 + nj * 8 + qcol2;
            float b0 = 0.f, b1 = 0.f;
            if (bias1) { b0 = bias1[n] + bias2[n]; b1 = bias1[n + 1] + bias2[n + 1]; }
#pragma unroll
            for (int mi = 0; mi < 2; mi++) {
                const int m = m0 + wm * 32 + mi * 16 + qrow;
                float2 v0, v1;
                v0.x = acc[mi][nj][0] + b0; v0.y = acc[mi][nj][1] + b1;
                v1.x = acc[mi][nj][2] + b0; v1.y = acc[mi][nj][3] + b1;
                *(float2*)(C + (size_t)m * ldc + n) = v0;
                *(float2*)(C + (size_t)(m + 8) * ldc + n) = v1;
            }
        }
    } else {
#pragma unroll
        for (int nj = 0; nj < 4; nj++) {
            const int n = j0 + wn * 32 + nj * 8 + qcol2;
#pragma unroll
            for (int mi = 0; mi < 2; mi++) {
                const int m = m0 + wm * 32 + mi * 16 + qrow;
                split2_store(Chi + (size_t)m * ldc + n, Clo + (size_t)m * ldc + n,
                             acc[mi][nj][0], acc[mi][nj][1]);
                split2_store(Chi + (size_t)(m + 8) * ldc + n, Clo + (size_t)(m + 8) * ldc + n,
                             acc[mi][nj][2], acc[mi][nj][3]);
            }
        }
    }
}

// ---------------------------------------------------------------------------
// splitters / weight-panel builders
// ---------------------------------------------------------------------------
__global__ void split_f32_kernel(const float* __restrict__ in,
                                 __nv_bfloat16* __restrict__ hi,
                                 __nv_bfloat16* __restrict__ lo, size_t n)
{
    size_t i = (size_t)blockIdx.x * blockDim.x + threadIdx.x;
    const size_t stride = (size_t)gridDim.x * blockDim.x;
    for (; i < n; i += stride) {
        float v = in[i];
        __nv_bfloat16 h = __float2bfloat16(v);
        hi[i] = h;
        lo[i] = __float2bfloat16(v - __bfloat162float(h));
    }
}
__global__ void build_Bp_kernel(const float* __restrict__ wq, const float* __restrict__ wkv,
                                const float* __restrict__ hq, const float* __restrict__ hkv)
{
    const int idx = blockIdx.x * 256 + threadIdx.x;   // k*3072 + n
    const int k = idx / 3072, n = idx - k * 3072;
    float v;
    if (n < 512)       v = wq[k * 512 + n];
    else if (n < 1536) v = wkv[k * 1024 + (n - 512)];
    else if (n < 2048) v = hq[k * 512 + (n - 1536)];
    else               v = hkv[k * 1024 + (n - 2048)];
    __nv_bfloat16 h = __float2bfloat16(v);
    g_Bph[(size_t)n * 256 + k] = h;
    g_Bpl[(size_t)n * 256 + k] = __float2bfloat16(v - __bfloat162float(h));
}
__global__ void build_Bo_kernel(const float* __restrict__ wo, const float* __restrict__ ho)
{
    const int idx = blockIdx.x * 256 + threadIdx.x;   // k*256 + n
    const int k = idx >> 8, n = idx & 255;
    float v = (k < 512) ? wo[k * 256 + n] : ho[(k - 512) * 256 + n];
    __nv_bfloat16 h = __float2bfloat16(v);
    g_Boh[(size_t)n * 1024 + k] = h;
    g_Bol[(size_t)n * 1024 + k] = __float2bfloat16(v - __bfloat162float(h));
}

// ---------------------------------------------------------------------------
// Column attention (w branch). One block per (cw, H). Unchanged.
// ---------------------------------------------------------------------------
#define ATTNW_SMEM (6 * 16384)

__global__ __launch_bounds__(256) void attn_w_mma()
{
    extern __shared__ char smem[];
    const uint32_t sb = smem_to_u32(smem);
    const int cw = blockIdx.x, H = blockIdx.y;
    const int tid = threadIdx.x, lane = tid & 31, wid = tid >> 5;

#pragma unroll
    for (int t = 0; t < 6; t++) {
        const __nv_bfloat16* src = (t & 1) ? g_Pl : g_Ph;
        const int coff = (t >> 1) * 512 + H * 64;
#pragma unroll
        for (int i = 0; i < 4; i++) {
            const int id = tid + i * 256;
            const int row = id & 127, g = id >> 7;
            CP_ASYNC16(sb + t * 16384 + row * 128 + ((g ^ (row & 7)) << 4),
                       src + (size_t)(row * 256 + cw) * PLD + coff + g * 8);
        }
    }
    CP_COMMIT(); CP_WAIT0();
    __syncthreads();

    const uint32_t sQh = sb, sQl = sb + 16384, sKh = sb + 32768,
                   sKl = sb + 49152, sVh = sb + 65536, sVl = sb + 81920;
    const int i0w = wid * 16;

    float acc[16][4];
#pragma unroll
    for (int i = 0; i < 16; i++)
#pragma unroll
        for (int u = 0; u < 4; u++) acc[i][u] = 0.f;

#pragma unroll
    for (int kb = 0; kb < 4; kb++) {
        const int lg = kb * 2 + (lane >> 4);
        const int ar = i0w + (lane & 15);
        const uint32_t aoff = ar * 128 + ((lg ^ (ar & 7)) << 4);
        uint32_t ah[4], al[4];
        LDMATRIX_X4(ah[0], ah[1], ah[2], ah[3], sQh + aoff);
        LDMATRIX_X4(al[0], al[1], al[2], al[3], sQl + aoff);
        uint32_t b[8][4];
#pragma unroll
        for (int nf = 0; nf < 8; nf++) {
            const int br = nf * 16 + (lane & 15);
            LDMATRIX_X4(b[nf][0], b[nf][1], b[nf][2], b[nf][3],
                        sKh + br * 128 + ((lg ^ (br & 7)) << 4));
        }
#pragma unroll
        for (int nf = 0; nf < 8; nf++) {
            MMA_BF16(acc[2 * nf],     ah[0], ah[1], ah[2], ah[3], b[nf][0], b[nf][2]);
            MMA_BF16(acc[2 * nf + 1], ah[0], ah[1], ah[2], ah[3], b[nf][1], b[nf][3]);
        }
#pragma unroll
        for (int nf = 0; nf < 8; nf++) {
            MMA_BF16(acc[2 * nf],     al[0], al[1], al[2], al[3], b[nf][0], b[nf][2]);
            MMA_BF16(acc[2 * nf + 1], al[0], al[1], al[2], al[3], b[nf][1], b[nf][3]);
        }
#pragma unroll
        for (int nf = 0; nf < 8; nf++) {
            const int br = nf * 16 + (lane & 15);
            LDMATRIX_X4(b[nf][0], b[nf][1], b[nf][2], b[nf][3],
                        sKl + br * 128 + ((lg ^ (br & 7)) << 4));
        }
#pragma unroll
        for (int nf = 0; nf < 8; nf++) {
            MMA_BF16(acc[2 * nf],     ah[0], ah[1], ah[2], ah[3], b[nf][0], b[nf][2]);
            MMA_BF16(acc[2 * nf + 1], ah[0], ah[1], ah[2], ah[3], b[nf][1], b[nf][3]);
        }
    }

    float mx0 = -1e30f, mx1 = -1e30f;
#pragma unroll
    for (int ni = 0; ni < 16; ni++) {
        acc[ni][0] *= 0.125f; acc[ni][1] *= 0.125f;
        acc[ni][2] *= 0.125f; acc[ni][3] *= 0.125f;
        mx0 = fmaxf(mx0, fmaxf(acc[ni][0], acc[ni][1]));
        mx1 = fmaxf(mx1, fmaxf(acc[ni][2], acc[ni][3]));
    }
    mx0 = fmaxf(mx0, __shfl_xor_sync(0xffffffffu, mx0, 1));
    mx0 = fmaxf(mx0, __shfl_xor_sync(0xffffffffu, mx0, 2));
    mx1 = fmaxf(mx1, __shfl_xor_sync(0xffffffffu, mx1, 1));
    mx1 = fmaxf(mx1, __shfl_xor_sync(0xffffffffu, mx1, 2));
    float s0 = 0.f, s1 = 0.f;
#pragma unroll
    for (int ni = 0; ni < 16; ni++) {
        float e;
        e = __expf(acc[ni][0] - mx0); acc[ni][0] = e; s0 += e;
        e = __expf(acc[ni][1] - mx0); acc[ni][1] = e; s0 += e;
        e = __expf(acc[ni][2] - mx1); acc[ni][2] = e; s1 += e;
        e = __expf(acc[ni][3] - mx1); acc[ni][3] = e; s1 += e;
    }
    s0 += __shfl_xor_sync(0xffffffffu, s0, 1);
    s0 += __shfl_xor_sync(0xffffffffu, s0, 2);
    s1 += __shfl_xor_sync(0xffffffffu, s1, 1);
    s1 += __shfl_xor_sync(0xffffffffu, s1, 2);
    const float inv0 = 1.f / s0, inv1 = 1.f / s1;

    uint32_t aph[8][4], apl[8][4];
#pragma unroll
    for (int kb = 0; kb < 8; kb++) {
        const int n0 = 2 * kb, n1 = n0 + 1;
        float p[8];
        p[0] = acc[n0][0] * inv0; p[1] = acc[n0][1] * inv0;
        p[2] = acc[n0][2] * inv1; p[3] = acc[n0][3] * inv1;
        p[4] = acc[n1][0] * inv0; p[5] = acc[n1][1] * inv0;
        p[6] = acc[n1][2] * inv1; p[7] = acc[n1][3] * inv1;
#pragma unroll
        for (int u = 0; u < 4; u++) {
            float a = p[2 * u], b = p[2 * u + 1];
            __nv_bfloat16 ha = __float2bfloat16(a), hb = __float2bfloat16(b);
            __nv_bfloat162 hh; hh.x = ha; hh.y = hb;
            aph[kb][u] = *reinterpret_cast<uint32_t*>(&hh);
            apl[kb][u] = pack_bf16x2(a - __bfloat162float(ha), b - __bfloat162float(hb));
        }
    }

    float acco[8][4];
#pragma unroll
    for (int i = 0; i < 8; i++)
#pragma unroll
        for (int u = 0; u < 4; u++) acco[i][u] = 0.f;

#pragma unroll
    for (int kb = 0; kb < 8; kb++) {
        const int jrow = kb * 16 + ((lane >> 3) & 1) * 8 + (lane & 7);
        uint32_t vb[4][4];
#pragma unroll
        for (int nfp = 0; nfp < 4; nfp++) {
            const int ncol = nfp * 16 + (lane >> 4) * 8;
            LDMATRIX_X4_T(vb[nfp][0], vb[nfp][1], vb[nfp][2], vb[nfp][3],
                          sVh + jrow * 128 + ((((ncol >> 3) ^ (jrow & 7))) << 4));
        }
#pragma unroll
        for (int nfp = 0; nfp < 4; nfp++) {
            MMA_BF16(acco[2 * nfp],     aph[kb][0], aph[kb][1], aph[kb][2], aph[kb][3], vb[nfp][0], vb[nfp][1]);
            MMA_BF16(acco[2 * nfp + 1], aph[kb][0], aph[kb][1], aph[kb][2], aph[kb][3], vb[nfp][2], vb[nfp][3]);
        }
#pragma unroll
        for (int nfp = 0; nfp < 4; nfp++) {
            MMA_BF16(acco[2 * nfp],     apl[kb][0], apl[kb][1], apl[kb][2], apl[kb][3], vb[nfp][0], vb[nfp][1]);
            MMA_BF16(acco[2 * nfp + 1], apl[kb][0], apl[kb][1], apl[kb][2], apl[kb][3], vb[nfp][2], vb[nfp][3]);
        }
#pragma unroll
        for (int nfp = 0; nfp < 4; nfp++) {
            const int ncol = nfp * 16 + (lane >> 4) * 8;
            LDMATRIX_X4_T(vb[nfp][0], vb[nfp][1], vb[nfp][2], vb[nfp][3],
                          sVl + jrow * 128 + ((((ncol >> 3) ^ (jrow & 7))) << 4));
        }
#pragma unroll
        for (int nfp = 0; nfp < 4; nfp++) {
            MMA_BF16(acco[2 * nfp],     aph[kb][0], aph[kb][1], aph[kb][2], aph[kb][3], vb[nfp][0], vb[nfp][1]);
            MMA_BF16(acco[2 * nfp + 1], aph[kb][0], aph[kb][1], aph[kb][2], aph[kb][3], vb[nfp][2], vb[nfp][3]);
        }
    }

    const int r0 = i0w + (lane >> 2), r1 = r0 + 8;
#pragma unroll
    for (int nf = 0; nf < 8; nf++) {
        const int c = H * 64 + nf * 8 + (lane & 3) * 2;
        const size_t t0 = (size_t)(r0 * 256 + cw) * OLD + c;
        const size_t t1 = (size_t)(r1 * 256 + cw) * OLD + c;
        split2_store(g_Ohi + t0, g_Olo + t0, acco[nf][0], acco[nf][1]);
        split2_store(g_Ohi + t1, g_Olo + t1, acco[nf][2], acco[nf][3]);
    }
}

// ---------------------------------------------------------------------------
// Tied row attention dots: split-K over r. 2 CTAs/SM. Unchanged.
// ---------------------------------------------------------------------------
#define DOTS_SMEM (3 * 32768)

__global__ __launch_bounds__(256, 2) void dots_h_mma()
{
    extern __shared__ char smem[];
    const uint32_t sb = smem_to_u32(smem);
    const int tid = threadIdx.x, lane = tid & 31, wid = tid >> 5;
    const int wm = wid & 3, wn = wid >> 2;
    const int i0 = (blockIdx.x & 1) * 128, j0 = (blockIdx.x >> 1) * 128;
    const int H = blockIdx.y, sp = blockIdx.z;
    const int rbase = sp * 32;
    const int NC = 64;

    float acc[2][8][4];
#pragma unroll
    for (int i = 0; i < 2; i++)
#pragma unroll
        for (int j = 0; j < 8; j++)
#pragma unroll
            for (int u = 0; u < 4; u++) acc[i][j][u] = 0.f;

    auto load_chunk = [&](int c, int s) {
        const int r = rbase + (c >> 1), dhc = (c & 1) * 32;
        const size_t abase = ((size_t)(r * 256 + i0)) * PLD + 1536 + H * 64 + dhc;
        const size_t bbase = ((size_t)(r * 256 + j0)) * PLD + 2048 + H * 64 + dhc;
        const uint32_t sA = sb + s * 32768, sB = sA + 16384;
#pragma unroll
        for (int i = 0; i < 4; i++) {
            const int id = tid + i * 256;
            const int row = id & 127, g = id >> 7;
            const uint32_t off = row * 128 + ((g ^ (row & 7)) << 4);
            const __nv_bfloat16* src = (g < 4) ? g_Ph : g_Pl;
            CP_ASYNC16(sA + off, src + abase + (size_t)row * PLD + (g & 3) * 8);
            CP_ASYNC16(sB + off, src + bbase + (size_t)row * PLD + (g & 3) * 8);
        }
        CP_COMMIT();
    };

    load_chunk(0, 0);
    load_chunk(1, 1);
    for (int c = 0; c < NC; c++) {
        if (c < NC - 1) { CP_WAIT1(); } else { CP_WAIT0(); }
        __syncthreads();
        if (c + 2 < NC) load_chunk(c + 2, (c + 2) % 3);
        const uint32_t sA = sb + (c % 3) * 32768;
        compute_chunk128(sA, sA + 16384, lane, wm, wn, acc);
    }

    float* Cp = g_Shp + (size_t)sp * 524288 + (size_t)H * 65536;
    const int qrow = lane >> 2, qcol2 = (lane & 3) * 2;
#pragma unroll
    for (int nj = 0; nj < 8; nj++) {
        const int n = j0 + wn * 64 + nj * 8 + qcol2;
#pragma unroll
        for (int mi = 0; mi < 2; mi++) {
            const int m = i0 + wm * 32 + mi * 16 + qrow;
            float2 v0, v1;
            v0.x = acc[mi][nj][0]; v0.y = acc[mi][nj][1];
            v1.x = acc[mi][nj][2]; v1.y = acc[mi][nj][3];
            *(float2*)(Cp + m * 256 + n) = v0;
            *(float2*)(Cp + (m + 8) * 256 + n) = v1;
        }
    }
}

// Sum 4 partials, scale, softmax over 256, emit bf16 hi/lo probs.
__global__ __launch_bounds__(256) void softmax_h_kernel()
{
    const size_t base = (size_t)blockIdx.x * 256;
    const int t = threadIdx.x;
    __shared__ float red[256];
    float v = (g_Shp[base + t] + g_Shp[524288 + base + t] +
               g_Shp[2 * 524288 + base + t] + g_Shp[3 * 524288 + base + t]) * TSC;
    red[t] = v;
    __syncthreads();
#pragma unroll
    for (int s = 128; s > 0; s >>= 1) {
        if (t < s) red[t] = fmaxf(red[t], red[t + s]);
        __syncthreads();
    }
    const float m = red[0];
    __syncthreads();
    const float e = __expf(v - m);
    red[t] = e;
    __syncthreads();
#pragma unroll
    for (int s = 128; s > 0; s >>= 1) {
        if (t < s) red[t] += red[t + s];
        __syncthreads();
    }
    const float p = e / red[0];
    const __nv_bfloat16 h = __float2bfloat16(p);
    g_Shh[base + t] = h;
    g_Shl[base + t] = __float2bfloat16(p - __bfloat162float(h));
}

// ---------------------------------------------------------------------------
// Tied row attention AV. 2 CTAs/SM. Unchanged.
// ---------------------------------------------------------------------------
#define AV_SMEM (2 * 40960)   // 80 KB

__global__ __launch_bounds__(256, 2) void av_h_mma()
{
    extern __shared__ char smem[];
    const uint32_t sb = smem_to_u32(smem);
    const int r = blockIdx.x, H = blockIdx.y;
    const int tid = threadIdx.x, lane = tid & 31, wid = tid >> 5;
    const int i0w = wid * 32;
    const int NC = 8;

    float acc[2][8][4];
#pragma unroll
    for (int i = 0; i < 2; i++)
#pragma unroll
        for (int j = 0; j < 8; j++)
#pragma unroll
            for (int u = 0; u < 4; u++) acc[i][j][u] = 0.f;

    auto load_chunk = [&](int c, int s) {
        const int jc = c << 5;
        const uint32_t sA = sb + s * 40960, sV = sA + 32768;
#pragma unroll
        for (int i = 0; i < 8; i++) {
            const int id = tid + i * 256;
            const int row = id & 255, g = id >> 8;
            const __nv_bfloat16* src = (g < 4) ? g_Shh : g_Shl;
            CP_ASYNC16(sA + row * 128 + ((g ^ (row & 7)) << 4),
                       src + (size_t)H * 65536 + row * 256 + jc + (g & 3) * 8);
        }
#pragma unroll
        for (int i = 0; i < 2; i++) {
            const int id = tid + i * 256;
            const int jrow = id & 31, g = (id >> 5) & 7, half = id >> 8;
            const __nv_bfloat16* src = half ? g_Pl : g_Ph;
            CP_ASYNC16(sV + half * 4096 + jrow * 128 + ((g ^ (jrow & 7)) << 4),
                       src + (size_t)(r * 256 + jc + jrow) * PLD + 2560 + H * 64 + g * 8);
        }
        CP_COMMIT();
    };

    load_chunk(0, 0);
    load_chunk(1, 1);
    for (int c = 0; c < NC; c++) {
        if (c + 1 < NC) { CP_WAIT1(); } else { CP_WAIT0(); }
        __syncthreads();
        const uint32_t sA = sb + (c & 1) * 40960, sV = sA + 32768;
#pragma unroll
        for (int kb = 0; kb < 2; kb++) {
            const int lg = kb * 2 + (lane >> 4);
            uint32_t ah[2][4], al[2][4];
#pragma unroll
            for (int mi = 0; mi < 2; mi++) {
                const int row = i0w + mi * 16 + (lane & 15);
                LDMATRIX_X4(ah[mi][0], ah[mi][1], ah[mi][2], ah[mi][3],
                            sA + row * 128 + ((lg ^ (row & 7)) << 4));
                LDMATRIX_X4(al[mi][0], al[mi][1], al[mi][2], al[mi][3],
                            sA + row * 128 + (((lg + 4) ^ (row & 7)) << 4));
            }
            const int jrow = kb * 16 + ((lane >> 3) & 1) * 8 + (lane & 7);
            uint32_t vb[4][4];
#pragma unroll
            for (int nfp = 0; nfp < 4; nfp++) {
                const int ncol = nfp * 16 + (lane >> 4) * 8;
                LDMATRIX_X4_T(vb[nfp][0], vb[nfp][1], vb[nfp][2], vb[nfp][3],
                              sV + jrow * 128 + ((((ncol >> 3) ^ (jrow & 7))) << 4));
            }
#pragma unroll
            for (int nfp = 0; nfp < 4; nfp++)
#pragma unroll
                for (int mi = 0; mi < 2; mi++) {
                    MMA_BF16(acc[mi][2 * nfp],     ah[mi][0], ah[mi][1], ah[mi][2], ah[mi][3], vb[nfp][0], vb[nfp][1]);
                    MMA_BF16(acc[mi][2 * nfp + 1], ah[mi][0], ah[mi][1], ah[mi][2], ah[mi][3], vb[nfp][2], vb[nfp][3]);
                }
#pragma unroll
            for (int nfp = 0; nfp < 4; nfp++)
#pragma unroll
                for (int mi = 0; mi < 2; mi++) {
                    MMA_BF16(acc[mi][2 * nfp],     al[mi][0], al[mi][1], al[mi][2], al[mi][3], vb[nfp][0], vb[nfp][1]);
                    MMA_BF16(acc[mi][2 * nfp + 1], al[mi][0], al[mi][1], al[mi][2], al[mi][3], vb[nfp][2], vb[nfp][3]);
                }
#pragma unroll
            for (int nfp = 0; nfp < 4; nfp++) {
                const int ncol = nfp * 16 + (lane >> 4) * 8;
                LDMATRIX_X4_T(vb[nfp][0], vb[nfp][1], vb[nfp][2], vb[nfp][3],
                              sV + 4096 + jrow * 128 + ((((ncol >> 3) ^ (jrow & 7))) << 4));
            }
#pragma unroll
            for (int nfp = 0; nfp < 4; nfp++)
#pragma unroll
                for (int mi = 0; mi < 2; mi++) {
                    MMA_BF16(acc[mi][2 * nfp],     ah[mi][0], ah[mi][1], ah[mi][2], ah[mi][3], vb[nfp][0], vb[nfp][1]);
                    MMA_BF16(acc[mi][2 * nfp + 1], ah[mi][0], ah[mi][1], ah[mi][2], ah[mi][3], vb[nfp][2], vb[nfp][3]);
                }
        }
        __syncthreads();
        if (c + 2 < NC) load_chunk(c + 2, c & 1);
    }

    const int qrow = lane >> 2, qcol2 = (lane & 3) * 2;
#pragma unroll
    for (int nf = 0; nf < 8; nf++) {
        const int c = 512 + H * 64 + nf * 8 + qcol2;
#pragma unroll
        for (int mi = 0; mi < 2; mi++) {
            const int i = i0w + mi * 16 + qrow;
            const size_t t0 = (size_t)(r * 256 + i) * OLD + c;
            const size_t t1 = (size_t)(r * 256 + i + 8) * OLD + c;
            split2_store(g_Ohi + t0, g_Olo + t0, acc[mi][nf][0], acc[mi][nf][1]);
            split2_store(g_Ohi + t1, g_Olo + t1, acc[mi][nf][2], acc[mi][nf][3]);
        }
    }
}

// ---------------------------------------------------------------------------
extern "C" void kernel_launch(void* const* d_in, const int* in_sizes, int n_in,
                              void* d_out, int out_size)
{
    const float* x      = (const float*)d_in[0];
    const float* wq_w   = (const float*)d_in[1];
    const float* wkv_w  = (const float*)d_in[2];
    const float* wout_w = (const float*)d_in[3];
    const float* wout_b = (const float*)d_in[4];
    const float* hq_w   = (const float*)d_in[5];
    const float* hkv_w  = (const float*)d_in[6];
    const float* hout_w = (const float*)d_in[7];
    const float* hout_b = (const float*)d_in[8];
    float* out = (float*)d_out;

    __nv_bfloat16 *xh, *xl, *Bph, *Bpl, *Ph, *Pl, *Ohi, *Olo, *Boh, *Bol;
    cudaGetSymbolAddress((void**)&xh, g_xh);
    cudaGetSymbolAddress((void**)&xl, g_xl);
    cudaGetSymbolAddress((void**)&Bph, g_Bph);
    cudaGetSymbolAddress((void**)&Bpl, g_Bpl);
    cudaGetSymbolAddress((void**)&Ph, g_Ph);
    cudaGetSymbolAddress((void**)&Pl, g_Pl);
    cudaGetSymbolAddress((void**)&Ohi, g_Ohi);
    cudaGetSymbolAddress((void**)&Olo, g_Olo);
    cudaGetSymbolAddress((void**)&Boh, g_Boh);
    cudaGetSymbolAddress((void**)&Bol, g_Bol);

    cudaFuncSetAttribute(gemm_mma, cudaFuncAttributeMaxDynamicSharedMemorySize, GEMM_SMEM);
    cudaFuncSetAttribute(attn_w_mma, cudaFuncAttributeMaxDynamicSharedMemorySize, ATTNW_SMEM);
    cudaFuncSetAttribute(dots_h_mma, cudaFuncAttributeMaxDynamicSharedMemorySize, DOTS_SMEM);
    cudaFuncSetAttribute(av_h_mma, cudaFuncAttributeMaxDynamicSharedMemorySize, AV_SMEM);

    // 1) splits + weight panels
    split_f32_kernel<<<4096, 256>>>(x, xh, xl, (size_t)NTOK * DIMD);
    build_Bp_kernel<<<3072, 256>>>(wq_w, wkv_w, hq_w, hkv_w);
    build_Bo_kernel<<<1024, 256>>>(wout_w, hout_w);

    // 2) projections -> P (bf16 hi/lo): tiles 128x64, grid (3072/64, 32768/128)
    gemm_mma<<<dim3(48, 256), 256, GEMM_SMEM>>>(xh, xl, DIMD, Bph, Bpl, DIMD,
                                                nullptr, Ph, Pl, PLD, DIMD,
                                                nullptr, nullptr);

    // 3) column attention (w branch) -> O cols [0,512)
    attn_w_mma<<<dim3(256, 8), 256, ATTNW_SMEM>>>();

    // 4) tied row attention (h branch) -> O cols [512,1024)
    dots_h_mma<<<dim3(4, 8, 4), 256, DOTS_SMEM>>>();
    softmax_h_kernel<<<2048, 256>>>();
    av_h_mma<<<dim3(128, 8), 256, AV_SMEM>>>();

    // 5) out = O @ [wout;hout] + biases: tiles 128x64, grid (256/64, 32768/128)
    gemm_mma<<<dim3(4, 256), 256, GEMM_SMEM>>>(Ohi, Olo, OLD, Boh, Bol, 1024,
                                               out, nullptr, nullptr, DIMD, 1024,
                                               wout_b, hout_b);
}

// round 10
// speedup vs baseline: 1.0798x; 1.0798x over previous
#include <cuda_runtime.h>
#include <cuda_bf16.h>
#include <cstdint>

#define NTOK  32768
#define DIMD  256
#define HEADS 8
#define MSAH  128
#define MSAW  256
#define PLD   3072   // P cols: [wq(512) | wk@512 | wv@1024 | hq@1536 | hk@2048 | hv@2560]
#define OLD   1024   // O cols: [Ow(512) | Oh(512)]
#define TSC   0.011048543456039806f  // 64^-0.5 * 128^-0.5
#define DSPLIT 8     // dots_h split-K factor

// ---------------------------------------------------------------------------
// Scratch
// ---------------------------------------------------------------------------
__device__ __nv_bfloat16 g_Ph[(size_t)NTOK * PLD];
__device__ __nv_bfloat16 g_Pl[(size_t)NTOK * PLD];
__device__ float g_Shp[DSPLIT * HEADS * 256 * 256];   // 16 MB partials
__device__ __nv_bfloat16 g_Shh[HEADS * 256 * 256];
__device__ __nv_bfloat16 g_Shl[HEADS * 256 * 256];
__device__ __nv_bfloat16 g_xh[(size_t)NTOK * DIMD];
__device__ __nv_bfloat16 g_xl[(size_t)NTOK * DIMD];
__device__ __nv_bfloat16 g_Bph[3072 * 256];
__device__ __nv_bfloat16 g_Bpl[3072 * 256];
__device__ __nv_bfloat16 g_Ohi[(size_t)NTOK * OLD];
__device__ __nv_bfloat16 g_Olo[(size_t)NTOK * OLD];
__device__ __nv_bfloat16 g_Boh[256 * 1024];
__device__ __nv_bfloat16 g_Bol[256 * 1024];

// ---------------------------------------------------------------------------
// PTX helpers (compute_103-safe)
// ---------------------------------------------------------------------------
__device__ __forceinline__ uint32_t smem_to_u32(const void* p) {
    uint32_t a;
    asm("{ .reg .u64 t; cvta.to.shared.u64 t, %1; cvt.u32.u64 %0, t; }" : "=r"(a) : "l"(p));
    return a;
}
#define CP_ASYNC16(dst, src) \
    asm volatile("cp.async.cg.shared.global [%0], [%1], 16;" :: "r"(dst), "l"(src) : "memory")
#define CP_COMMIT() asm volatile("cp.async.commit_group;" ::: "memory")
#define CP_WAIT0()  asm volatile("cp.async.wait_group 0;" ::: "memory")
#define CP_WAIT1()  asm volatile("cp.async.wait_group 1;" ::: "memory")

#define LDMATRIX_X4(d0, d1, d2, d3, addr) \
    asm volatile("ldmatrix.sync.aligned.m8n8.x4.shared.b16 {%0,%1,%2,%3}, [%4];" \
        : "=r"(d0), "=r"(d1), "=r"(d2), "=r"(d3) : "r"(addr))
#define LDMATRIX_X4_T(d0, d1, d2, d3, addr) \
    asm volatile("ldmatrix.sync.aligned.m8n8.x4.trans.shared.b16 {%0,%1,%2,%3}, [%4];" \
        : "=r"(d0), "=r"(d1), "=r"(d2), "=r"(d3) : "r"(addr))

#define MMA_BF16(c, a0, a1, a2, a3, b0, b1) \
    asm volatile("mma.sync.aligned.m16n8k16.row.col.f32.bf16.bf16.f32 " \
        "{%0,%1,%2,%3}, {%4,%5,%6,%7}, {%8,%9}, {%0,%1,%2,%3};" \
        : "+f"((c)[0]), "+f"((c)[1]), "+f"((c)[2]), "+f"((c)[3]) \
        : "r"(a0), "r"(a1), "r"(a2), "r"(a3), "r"(b0), "r"(b1))

__device__ __forceinline__ uint32_t pack_bf16x2(float lo, float hi) {
    __nv_bfloat162 t = __floats2bfloat162_rn(lo, hi);
    return *reinterpret_cast<uint32_t*>(&t);
}
__device__ __forceinline__ void split2_store(__nv_bfloat16* hi, __nv_bfloat16* lo,
                                             float a, float b) {
    __nv_bfloat16 ha = __float2bfloat16(a), hb = __float2bfloat16(b);
    __nv_bfloat162 h; h.x = ha; h.y = hb;
    *reinterpret_cast<__nv_bfloat162*>(hi) = h;
    __nv_bfloat162 l;
    l.x = __float2bfloat16(a - __bfloat162float(ha));
    l.y = __float2bfloat16(b - __bfloat162float(hb));
    *reinterpret_cast<__nv_bfloat162*>(lo) = l;
}

// ---------------------------------------------------------------------------
// 128x128 tile compute: one 32-k chunk (granules 0-3 hi, 4-7 lo).
// Warp grid 4(m) x 2(n); warp tile 32x64; 3 term-major passes.
// ---------------------------------------------------------------------------
__device__ __forceinline__ void compute_chunk128(uint32_t sAst, uint32_t sBst,
                                                 int lane, int wm, int wn,
                                                 float acc[2][8][4])
{
#pragma unroll
    for (int kb = 0; kb < 2; kb++) {
        const int lg = kb * 2 + (lane >> 4);
        uint32_t ah[2][4], al[2][4];
#pragma unroll
        for (int mi = 0; mi < 2; mi++) {
            const int row = wm * 32 + mi * 16 + (lane & 15);
            LDMATRIX_X4(ah[mi][0], ah[mi][1], ah[mi][2], ah[mi][3],
                        sAst + row * 128 + (((lg) ^ (row & 7)) << 4));
            LDMATRIX_X4(al[mi][0], al[mi][1], al[mi][2], al[mi][3],
                        sAst + row * 128 + (((lg + 4) ^ (row & 7)) << 4));
        }
        uint32_t b[4][4];
#pragma unroll
        for (int nf = 0; nf < 4; nf++) {
            const int row = wn * 64 + nf * 16 + (lane & 15);
            LDMATRIX_X4(b[nf][0], b[nf][1], b[nf][2], b[nf][3],
                        sBst + row * 128 + (((lg) ^ (row & 7)) << 4));
        }
#pragma unroll
        for (int nf = 0; nf < 4; nf++)
#pragma unroll
            for (int mi = 0; mi < 2; mi++) {
                MMA_BF16(acc[mi][2 * nf],     ah[mi][0], ah[mi][1], ah[mi][2], ah[mi][3], b[nf][0], b[nf][2]);
                MMA_BF16(acc[mi][2 * nf + 1], ah[mi][0], ah[mi][1], ah[mi][2], ah[mi][3], b[nf][1], b[nf][3]);
            }
#pragma unroll
        for (int nf = 0; nf < 4; nf++)
#pragma unroll
            for (int mi = 0; mi < 2; mi++) {
                MMA_BF16(acc[mi][2 * nf],     al[mi][0], al[mi][1], al[mi][2], al[mi][3], b[nf][0], b[nf][2]);
                MMA_BF16(acc[mi][2 * nf + 1], al[mi][0], al[mi][1], al[mi][2], al[mi][3], b[nf][1], b[nf][3]);
            }
#pragma unroll
        for (int nf = 0; nf < 4; nf++) {
            const int row = wn * 64 + nf * 16 + (lane & 15);
            LDMATRIX_X4(b[nf][0], b[nf][1], b[nf][2], b[nf][3],
                        sBst + row * 128 + (((lg + 4) ^ (row & 7)) << 4));
        }
#pragma unroll
        for (int nf = 0; nf < 4; nf++)
#pragma unroll
            for (int mi = 0; mi < 2; mi++) {
                MMA_BF16(acc[mi][2 * nf],     ah[mi][0], ah[mi][1], ah[mi][2], ah[mi][3], b[nf][0], b[nf][2]);
                MMA_BF16(acc[mi][2 * nf + 1], ah[mi][0], ah[mi][1], ah[mi][2], ah[mi][3], b[nf][1], b[nf][3]);
            }
    }
}

// ---------------------------------------------------------------------------
// Fused hi/lo split-bf16 GEMM. Tile 128x128, 2 CTAs/SM (proven best config).
// ---------------------------------------------------------------------------
#define GEMM_SMEM (3 * 32768)

__global__ __launch_bounds__(256, 2)
void gemm_mma(const __nv_bfloat16* __restrict__ Ah, const __nv_bfloat16* __restrict__ Al, int lda,
              const __nv_bfloat16* __restrict__ Bh, const __nv_bfloat16* __restrict__ Bl, int ldb,
              float* __restrict__ C,
              __nv_bfloat16* __restrict__ Chi, __nv_bfloat16* __restrict__ Clo,
              int ldc, int K,
              const float* __restrict__ bias1, const float* __restrict__ bias2)
{
    extern __shared__ char smem[];
    const uint32_t sb = smem_to_u32(smem);
    const int tid = threadIdx.x, lane = tid & 31, wid = tid >> 5;
    const int wm = wid & 3, wn = wid >> 2;
    const int m0 = blockIdx.y * 128, j0 = blockIdx.x * 128;
    const int NC = K >> 5;

    float acc[2][8][4];
#pragma unroll
    for (int i = 0; i < 2; i++)
#pragma unroll
        for (int j = 0; j < 8; j++)
#pragma unroll
            for (int u = 0; u < 4; u++) acc[i][j][u] = 0.f;

    auto load_chunk = [&](int c, int s) {
        const int kc = c << 5;
        const uint32_t sA = sb + s * 32768, sB = sA + 16384;
#pragma unroll
        for (int i = 0; i < 4; i++) {
            const int id = tid + i * 256;
            const int row = id & 127, g = id >> 7;
            const uint32_t off = row * 128 + ((g ^ (row & 7)) << 4);
            const __nv_bfloat16* Asrc = (g < 4) ? Ah : Al;
            const __nv_bfloat16* Bsrc = (g < 4) ? Bh : Bl;
            CP_ASYNC16(sA + off, Asrc + (size_t)(m0 + row) * lda + kc + (g & 3) * 8);
            CP_ASYNC16(sB + off, Bsrc + (size_t)(j0 + row) * ldb + kc + (g & 3) * 8);
        }
        CP_COMMIT();
    };

    load_chunk(0, 0);
    load_chunk(1, 1);
    for (int c = 0; c < NC; c++) {
        if (c < NC - 1) { CP_WAIT1(); } else { CP_WAIT0(); }
        __syncthreads();
        if (c + 2 < NC) load_chunk(c + 2, (c + 2) % 3);
        const uint32_t sA = sb + (c % 3) * 32768;
        compute_chunk128(sA, sA + 16384, lane, wm, wn, acc);
    }

    const int qrow = lane >> 2, qcol2 = (lane & 3) * 2;
    if (C) {
#pragma unroll
        for (int nj = 0; nj < 8; nj++) {
            const int n = j0 + wn * 64 + nj * 8 + qcol2;
            float b0 = 0.f, b1 = 0.f;
            if (bias1) { b0 = bias1[n] + bias2[n]; b1 = bias1[n + 1] + bias2[n + 1]; }
#pragma unroll
            for (int mi = 0; mi < 2; mi++) {
                const int m = m0 + wm * 32 + mi * 16 + qrow;
                float2 v0, v1;
                v0.x = acc[mi][nj][0] + b0; v0.y = acc[mi][nj][1] + b1;
                v1.x = acc[mi][nj][2] + b0; v1.y = acc[mi][nj][3] + b1;
                *(float2*)(C + (size_t)m * ldc + n) = v0;
                *(float2*)(C + (size_t)(m + 8) * ldc + n) = v1;
            }
        }
    } else {
#pragma unroll
        for (int nj = 0; nj < 8; nj++) {
            const int n = j0 + wn * 64 + nj * 8 + qcol2;
#pragma unroll
            for (int mi = 0; mi < 2; mi++) {
                const int m = m0 + wm * 32 + mi * 16 + qrow;
                split2_store(Chi + (size_t)m * ldc + n, Clo + (size_t)m * ldc + n,
                             acc[mi][nj][0], acc[mi][nj][1]);
                split2_store(Chi + (size_t)(m + 8) * ldc + n, Clo + (size_t)(m + 8) * ldc + n,
                             acc[mi][nj][2], acc[mi][nj][3]);
            }
        }
    }
}

// ---------------------------------------------------------------------------
// splitters / weight-panel builders
// ---------------------------------------------------------------------------
__global__ void split_f32_kernel(const float* __restrict__ in,
                                 __nv_bfloat16* __restrict__ hi,
                                 __nv_bfloat16* __restrict__ lo, size_t n)
{
    size_t i = (size_t)blockIdx.x * blockDim.x + threadIdx.x;
    const size_t stride = (size_t)gridDim.x * blockDim.x;
    for (; i < n; i += stride) {
        float v = in[i];
        __nv_bfloat16 h = __float2bfloat16(v);
        hi[i] = h;
        lo[i] = __float2bfloat16(v - __bfloat162float(h));
    }
}
__global__ void build_Bp_kernel(const float* __restrict__ wq, const float* __restrict__ wkv,
                                const float* __restrict__ hq, const float* __restrict__ hkv)
{
    const int idx = blockIdx.x * 256 + threadIdx.x;   // k*3072 + n
    const int k = idx / 3072, n = idx - k * 3072;
    float v;
    if (n < 512)       v = wq[k * 512 + n];
    else if (n < 1536) v = wkv[k * 1024 + (n - 512)];
    else if (n < 2048) v = hq[k * 512 + (n - 1536)];
    else               v = hkv[k * 1024 + (n - 2048)];
    __nv_bfloat16 h = __float2bfloat16(v);
    g_Bph[(size_t)n * 256 + k] = h;
    g_Bpl[(size_t)n * 256 + k] = __float2bfloat16(v - __bfloat162float(h));
}
__global__ void build_Bo_kernel(const float* __restrict__ wo, const float* __restrict__ ho)
{
    const int idx = blockIdx.x * 256 + threadIdx.x;   // k*256 + n
    const int k = idx >> 8, n = idx & 255;
    float v = (k < 512) ? wo[k * 256 + n] : ho[(k - 512) * 256 + n];
    __nv_bfloat16 h = __float2bfloat16(v);
    g_Boh[(size_t)n * 1024 + k] = h;
    g_Bol[(size_t)n * 1024 + k] = __float2bfloat16(v - __bfloat162float(h));
}

// ---------------------------------------------------------------------------
// Column attention (w branch). One block per (cw, H).
// ---------------------------------------------------------------------------
#define ATTNW_SMEM (6 * 16384)

__global__ __launch_bounds__(256) void attn_w_mma()
{
    extern __shared__ char smem[];
    const uint32_t sb = smem_to_u32(smem);
    const int cw = blockIdx.x, H = blockIdx.y;
    const int tid = threadIdx.x, lane = tid & 31, wid = tid >> 5;

#pragma unroll
    for (int t = 0; t < 6; t++) {
        const __nv_bfloat16* src = (t & 1) ? g_Pl : g_Ph;
        const int coff = (t >> 1) * 512 + H * 64;
#pragma unroll
        for (int i = 0; i < 4; i++) {
            const int id = tid + i * 256;
            const int row = id & 127, g = id >> 7;
            CP_ASYNC16(sb + t * 16384 + row * 128 + ((g ^ (row & 7)) << 4),
                       src + (size_t)(row * 256 + cw) * PLD + coff + g * 8);
        }
    }
    CP_COMMIT(); CP_WAIT0();
    __syncthreads();

    const uint32_t sQh = sb, sQl = sb + 16384, sKh = sb + 32768,
                   sKl = sb + 49152, sVh = sb + 65536, sVl = sb + 81920;
    const int i0w = wid * 16;

    float acc[16][4];
#pragma unroll
    for (int i = 0; i < 16; i++)
#pragma unroll
        for (int u = 0; u < 4; u++) acc[i][u] = 0.f;

#pragma unroll
    for (int kb = 0; kb < 4; kb++) {
        const int lg = kb * 2 + (lane >> 4);
        const int ar = i0w + (lane & 15);
        const uint32_t aoff = ar * 128 + ((lg ^ (ar & 7)) << 4);
        uint32_t ah[4], al[4];
        LDMATRIX_X4(ah[0], ah[1], ah[2], ah[3], sQh + aoff);
        LDMATRIX_X4(al[0], al[1], al[2], al[3], sQl + aoff);
        uint32_t b[8][4];
#pragma unroll
        for (int nf = 0; nf < 8; nf++) {
            const int br = nf * 16 + (lane & 15);
            LDMATRIX_X4(b[nf][0], b[nf][1], b[nf][2], b[nf][3],
                        sKh + br * 128 + ((lg ^ (br & 7)) << 4));
        }
#pragma unroll
        for (int nf = 0; nf < 8; nf++) {
            MMA_BF16(acc[2 * nf],     ah[0], ah[1], ah[2], ah[3], b[nf][0], b[nf][2]);
            MMA_BF16(acc[2 * nf + 1], ah[0], ah[1], ah[2], ah[3], b[nf][1], b[nf][3]);
        }
#pragma unroll
        for (int nf = 0; nf < 8; nf++) {
            MMA_BF16(acc[2 * nf],     al[0], al[1], al[2], al[3], b[nf][0], b[nf][2]);
            MMA_BF16(acc[2 * nf + 1], al[0], al[1], al[2], al[3], b[nf][1], b[nf][3]);
        }
#pragma unroll
        for (int nf = 0; nf < 8; nf++) {
            const int br = nf * 16 + (lane & 15);
            LDMATRIX_X4(b[nf][0], b[nf][1], b[nf][2], b[nf][3],
                        sKl + br * 128 + ((lg ^ (br & 7)) << 4));
        }
#pragma unroll
        for (int nf = 0; nf < 8; nf++) {
            MMA_BF16(acc[2 * nf],     ah[0], ah[1], ah[2], ah[3], b[nf][0], b[nf][2]);
            MMA_BF16(acc[2 * nf + 1], ah[0], ah[1], ah[2], ah[3], b[nf][1], b[nf][3]);
        }
    }

    float mx0 = -1e30f, mx1 = -1e30f;
#pragma unroll
    for (int ni = 0; ni < 16; ni++) {
        acc[ni][0] *= 0.125f; acc[ni][1] *= 0.125f;
        acc[ni][2] *= 0.125f; acc[ni][3] *= 0.125f;
        mx0 = fmaxf(mx0, fmaxf(acc[ni][0], acc[ni][1]));
        mx1 = fmaxf(mx1, fmaxf(acc[ni][2], acc[ni][3]));
    }
    mx0 = fmaxf(mx0, __shfl_xor_sync(0xffffffffu, mx0, 1));
    mx0 = fmaxf(mx0, __shfl_xor_sync(0xffffffffu, mx0, 2));
    mx1 = fmaxf(mx1, __shfl_xor_sync(0xffffffffu, mx1, 1));
    mx1 = fmaxf(mx1, __shfl_xor_sync(0xffffffffu, mx1, 2));
    float s0 = 0.f, s1 = 0.f;
#pragma unroll
    for (int ni = 0; ni < 16; ni++) {
        float e;
        e = __expf(acc[ni][0] - mx0); acc[ni][0] = e; s0 += e;
        e = __expf(acc[ni][1] - mx0); acc[ni][1] = e; s0 += e;
        e = __expf(acc[ni][2] - mx1); acc[ni][2] = e; s1 += e;
        e = __expf(acc[ni][3] - mx1); acc[ni][3] = e; s1 += e;
    }
    s0 += __shfl_xor_sync(0xffffffffu, s0, 1);
    s0 += __shfl_xor_sync(0xffffffffu, s0, 2);
    s1 += __shfl_xor_sync(0xffffffffu, s1, 1);
    s1 += __shfl_xor_sync(0xffffffffu, s1, 2);
    const float inv0 = 1.f / s0, inv1 = 1.f / s1;

    uint32_t aph[8][4], apl[8][4];
#pragma unroll
    for (int kb = 0; kb < 8; kb++) {
        const int n0 = 2 * kb, n1 = n0 + 1;
        float p[8];
        p[0] = acc[n0][0] * inv0; p[1] = acc[n0][1] * inv0;
        p[2] = acc[n0][2] * inv1; p[3] = acc[n0][3] * inv1;
        p[4] = acc[n1][0] * inv0; p[5] = acc[n1][1] * inv0;
        p[6] = acc[n1][2] * inv1; p[7] = acc[n1][3] * inv1;
#pragma unroll
        for (int u = 0; u < 4; u++) {
            float a = p[2 * u], b = p[2 * u + 1];
            __nv_bfloat16 ha = __float2bfloat16(a), hb = __float2bfloat16(b);
            __nv_bfloat162 hh; hh.x = ha; hh.y = hb;
            aph[kb][u] = *reinterpret_cast<uint32_t*>(&hh);
            apl[kb][u] = pack_bf16x2(a - __bfloat162float(ha), b - __bfloat162float(hb));
        }
    }

    float acco[8][4];
#pragma unroll
    for (int i = 0; i < 8; i++)
#pragma unroll
        for (int u = 0; u < 4; u++) acco[i][u] = 0.f;

#pragma unroll
    for (int kb = 0; kb < 8; kb++) {
        const int jrow = kb * 16 + ((lane >> 3) & 1) * 8 + (lane & 7);
        uint32_t vb[4][4];
#pragma unroll
        for (int nfp = 0; nfp < 4; nfp++) {
            const int ncol = nfp * 16 + (lane >> 4) * 8;
            LDMATRIX_X4_T(vb[nfp][0], vb[nfp][1], vb[nfp][2], vb[nfp][3],
                          sVh + jrow * 128 + ((((ncol >> 3) ^ (jrow & 7))) << 4));
        }
#pragma unroll
        for (int nfp = 0; nfp < 4; nfp++) {
            MMA_BF16(acco[2 * nfp],     aph[kb][0], aph[kb][1], aph[kb][2], aph[kb][3], vb[nfp][0], vb[nfp][1]);
            MMA_BF16(acco[2 * nfp + 1], aph[kb][0], aph[kb][1], aph[kb][2], aph[kb][3], vb[nfp][2], vb[nfp][3]);
        }
#pragma unroll
        for (int nfp = 0; nfp < 4; nfp++) {
            MMA_BF16(acco[2 * nfp],     apl[kb][0], apl[kb][1], apl[kb][2], apl[kb][3], vb[nfp][0], vb[nfp][1]);
            MMA_BF16(acco[2 * nfp + 1], apl[kb][0], apl[kb][1], apl[kb][2], apl[kb][3], vb[nfp][2], vb[nfp][3]);
        }
#pragma unroll
        for (int nfp = 0; nfp < 4; nfp++) {
            const int ncol = nfp * 16 + (lane >> 4) * 8;
            LDMATRIX_X4_T(vb[nfp][0], vb[nfp][1], vb[nfp][2], vb[nfp][3],
                          sVl + jrow * 128 + ((((ncol >> 3) ^ (jrow & 7))) << 4));
        }
#pragma unroll
        for (int nfp = 0; nfp < 4; nfp++) {
            MMA_BF16(acco[2 * nfp],     aph[kb][0], aph[kb][1], aph[kb][2], aph[kb][3], vb[nfp][0], vb[nfp][1]);
            MMA_BF16(acco[2 * nfp + 1], aph[kb][0], aph[kb][1], aph[kb][2], aph[kb][3], vb[nfp][2], vb[nfp][3]);
        }
    }

    const int r0 = i0w + (lane >> 2), r1 = r0 + 8;
#pragma unroll
    for (int nf = 0; nf < 8; nf++) {
        const int c = H * 64 + nf * 8 + (lane & 3) * 2;
        const size_t t0 = (size_t)(r0 * 256 + cw) * OLD + c;
        const size_t t1 = (size_t)(r1 * 256 + cw) * OLD + c;
        split2_store(g_Ohi + t0, g_Olo + t0, acco[nf][0], acco[nf][1]);
        split2_store(g_Ohi + t1, g_Olo + t1, acco[nf][2], acco[nf][3]);
    }
}

// ---------------------------------------------------------------------------
// Tied row attention dots: split-K over r, DSPLIT=8 -> grid 256 fills chip.
// ---------------------------------------------------------------------------
#define DOTS_SMEM (3 * 32768)

__global__ __launch_bounds__(256, 2) void dots_h_mma()
{
    extern __shared__ char smem[];
    const uint32_t sb = smem_to_u32(smem);
    const int tid = threadIdx.x, lane = tid & 31, wid = tid >> 5;
    const int wm = wid & 3, wn = wid >> 2;
    const int i0 = (blockIdx.x & 1) * 128, j0 = (blockIdx.x >> 1) * 128;
    const int H = blockIdx.y, sp = blockIdx.z;
    const int rbase = sp * (128 / DSPLIT);
    const int NC = (128 / DSPLIT) * 2;   // 16 r x 2 dh-halves = 32

    float acc[2][8][4];
#pragma unroll
    for (int i = 0; i < 2; i++)
#pragma unroll
        for (int j = 0; j < 8; j++)
#pragma unroll
            for (int u = 0; u < 4; u++) acc[i][j][u] = 0.f;

    auto load_chunk = [&](int c, int s) {
        const int r = rbase + (c >> 1), dhc = (c & 1) * 32;
        const size_t abase = ((size_t)(r * 256 + i0)) * PLD + 1536 + H * 64 + dhc;
        const size_t bbase = ((size_t)(r * 256 + j0)) * PLD + 2048 + H * 64 + dhc;
        const uint32_t sA = sb + s * 32768, sB = sA + 16384;
#pragma unroll
        for (int i = 0; i < 4; i++) {
            const int id = tid + i * 256;
            const int row = id & 127, g = id >> 7;
            const uint32_t off = row * 128 + ((g ^ (row & 7)) << 4);
            const __nv_bfloat16* src = (g < 4) ? g_Ph : g_Pl;
            CP_ASYNC16(sA + off, src + abase + (size_t)row * PLD + (g & 3) * 8);
            CP_ASYNC16(sB + off, src + bbase + (size_t)row * PLD + (g & 3) * 8);
        }
        CP_COMMIT();
    };

    load_chunk(0, 0);
    load_chunk(1, 1);
    for (int c = 0; c < NC; c++) {
        if (c < NC - 1) { CP_WAIT1(); } else { CP_WAIT0(); }
        __syncthreads();
        if (c + 2 < NC) load_chunk(c + 2, (c + 2) % 3);
        const uint32_t sA = sb + (c % 3) * 32768;
        compute_chunk128(sA, sA + 16384, lane, wm, wn, acc);
    }

    float* Cp = g_Shp + (size_t)sp * 524288 + (size_t)H * 65536;
    const int qrow = lane >> 2, qcol2 = (lane & 3) * 2;
#pragma unroll
    for (int nj = 0; nj < 8; nj++) {
        const int n = j0 + wn * 64 + nj * 8 + qcol2;
#pragma unroll
        for (int mi = 0; mi < 2; mi++) {
            const int m = i0 + wm * 32 + mi * 16 + qrow;
            float2 v0, v1;
            v0.x = acc[mi][nj][0]; v0.y = acc[mi][nj][1];
            v1.x = acc[mi][nj][2]; v1.y = acc[mi][nj][3];
            *(float2*)(Cp + m * 256 + n) = v0;
            *(float2*)(Cp + (m + 8) * 256 + n) = v1;
        }
    }
}

// Sum DSPLIT partials, scale, softmax over 256, emit bf16 hi/lo probs.
__global__ __launch_bounds__(256) void softmax_h_kernel()
{
    const size_t base = (size_t)blockIdx.x * 256;
    const int t = threadIdx.x;
    __shared__ float red[256];
    float v = 0.f;
#pragma unroll
    for (int sp = 0; sp < DSPLIT; sp++)
        v += g_Shp[(size_t)sp * 524288 + base + t];
    v *= TSC;
    red[t] = v;
    __syncthreads();
#pragma unroll
    for (int s = 128; s > 0; s >>= 1) {
        if (t < s) red[t] = fmaxf(red[t], red[t + s]);
        __syncthreads();
    }
    const float m = red[0];
    __syncthreads();
    const float e = __expf(v - m);
    red[t] = e;
    __syncthreads();
#pragma unroll
    for (int s = 128; s > 0; s >>= 1) {
        if (t < s) red[t] += red[t + s];
        __syncthreads();
    }
    const float p = e / red[0];
    const __nv_bfloat16 h = __float2bfloat16(p);
    g_Shh[base + t] = h;
    g_Shl[base + t] = __float2bfloat16(p - __bfloat162float(h));
}

// ---------------------------------------------------------------------------
// Tied row attention AV. 2 CTAs/SM.
// ---------------------------------------------------------------------------
#define AV_SMEM (2 * 40960)   // 80 KB

__global__ __launch_bounds__(256, 2) void av_h_mma()
{
    extern __shared__ char smem[];
    const uint32_t sb = smem_to_u32(smem);
    const int r = blockIdx.x, H = blockIdx.y;
    const int tid = threadIdx.x, lane = tid & 31, wid = tid >> 5;
    const int i0w = wid * 32;
    const int NC = 8;

    float acc[2][8][4];
#pragma unroll
    for (int i = 0; i < 2; i++)
#pragma unroll
        for (int j = 0; j < 8; j++)
#pragma unroll
            for (int u = 0; u < 4; u++) acc[i][j][u] = 0.f;

    auto load_chunk = [&](int c, int s) {
        const int jc = c << 5;
        const uint32_t sA = sb + s * 40960, sV = sA + 32768;
#pragma unroll
        for (int i = 0; i < 8; i++) {
            const int id = tid + i * 256;
            const int row = id & 255, g = id >> 8;
            const __nv_bfloat16* src = (g < 4) ? g_Shh : g_Shl;
            CP_ASYNC16(sA + row * 128 + ((g ^ (row & 7)) << 4),
                       src + (size_t)H * 65536 + row * 256 + jc + (g & 3) * 8);
        }
#pragma unroll
        for (int i = 0; i < 2; i++) {
            const int id = tid + i * 256;
            const int jrow = id & 31, g = (id >> 5) & 7, half = id >> 8;
            const __nv_bfloat16* src = half ? g_Pl : g_Ph;
            CP_ASYNC16(sV + half * 4096 + jrow * 128 + ((g ^ (jrow & 7)) << 4),
                       src + (size_t)(r * 256 + jc + jrow) * PLD + 2560 + H * 64 + g * 8);
        }
        CP_COMMIT();
    };

    load_chunk(0, 0);
    load_chunk(1, 1);
    for (int c = 0; c < NC; c++) {
        if (c + 1 < NC) { CP_WAIT1(); } else { CP_WAIT0(); }
        __syncthreads();
        const uint32_t sA = sb + (c & 1) * 40960, sV = sA + 32768;
#pragma unroll
        for (int kb = 0; kb < 2; kb++) {
            const int lg = kb * 2 + (lane >> 4);
            uint32_t ah[2][4], al[2][4];
#pragma unroll
            for (int mi = 0; mi < 2; mi++) {
                const int row = i0w + mi * 16 + (lane & 15);
                LDMATRIX_X4(ah[mi][0], ah[mi][1], ah[mi][2], ah[mi][3],
                            sA + row * 128 + ((lg ^ (row & 7)) << 4));
                LDMATRIX_X4(al[mi][0], al[mi][1], al[mi][2], al[mi][3],
                            sA + row * 128 + (((lg + 4) ^ (row & 7)) << 4));
            }
            const int jrow = kb * 16 + ((lane >> 3) & 1) * 8 + (lane & 7);
            uint32_t vb[4][4];
#pragma unroll
            for (int nfp = 0; nfp < 4; nfp++) {
                const int ncol = nfp * 16 + (lane >> 4) * 8;
                LDMATRIX_X4_T(vb[nfp][0], vb[nfp][1], vb[nfp][2], vb[nfp][3],
                              sV + jrow * 128 + ((((ncol >> 3) ^ (jrow & 7))) << 4));
            }
#pragma unroll
            for (int nfp = 0; nfp < 4; nfp++)
#pragma unroll
                for (int mi = 0; mi < 2; mi++) {
                    MMA_BF16(acc[mi][2 * nfp],     ah[mi][0], ah[mi][1], ah[mi][2], ah[mi][3], vb[nfp][0], vb[nfp][1]);
                    MMA_BF16(acc[mi][2 * nfp + 1], ah[mi][0], ah[mi][1], ah[mi][2], ah[mi][3], vb[nfp][2], vb[nfp][3]);
                }
#pragma unroll
            for (int nfp = 0; nfp < 4; nfp++)
#pragma unroll
                for (int mi = 0; mi < 2; mi++) {
                    MMA_BF16(acc[mi][2 * nfp],     al[mi][0], al[mi][1], al[mi][2], al[mi][3], vb[nfp][0], vb[nfp][1]);
                    MMA_BF16(acc[mi][2 * nfp + 1], al[mi][0], al[mi][1], al[mi][2], al[mi][3], vb[nfp][2], vb[nfp][3]);
                }
#pragma unroll
            for (int nfp = 0; nfp < 4; nfp++) {
                const int ncol = nfp * 16 + (lane >> 4) * 8;
                LDMATRIX_X4_T(vb[nfp][0], vb[nfp][1], vb[nfp][2], vb[nfp][3],
                              sV + 4096 + jrow * 128 + ((((ncol >> 3) ^ (jrow & 7))) << 4));
            }
#pragma unroll
            for (int nfp = 0; nfp < 4; nfp++)
#pragma unroll
                for (int mi = 0; mi < 2; mi++) {
                    MMA_BF16(acc[mi][2 * nfp],     ah[mi][0], ah[mi][1], ah[mi][2], ah[mi][3], vb[nfp][0], vb[nfp][1]);
                    MMA_BF16(acc[mi][2 * nfp + 1], ah[mi][0], ah[mi][1], ah[mi][2], ah[mi][3], vb[nfp][2], vb[nfp][3]);
                }
        }
        __syncthreads();
        if (c + 2 < NC) load_chunk(c + 2, c & 1);
    }

    const int qrow = lane >> 2, qcol2 = (lane & 3) * 2;
#pragma unroll
    for (int nf = 0; nf < 8; nf++) {
        const int c = 512 + H * 64 + nf * 8 + qcol2;
#pragma unroll
        for (int mi = 0; mi < 2; mi++) {
            const int i = i0w + mi * 16 + qrow;
            const size_t t0 = (size_t)(r * 256 + i) * OLD + c;
            const size_t t1 = (size_t)(r * 256 + i + 8) * OLD + c;
            split2_store(g_Ohi + t0, g_Olo + t0, acc[mi][nf][0], acc[mi][nf][1]);
            split2_store(g_Ohi + t1, g_Olo + t1, acc[mi][nf][2], acc[mi][nf][3]);
        }
    }
}

// ---------------------------------------------------------------------------
extern "C" void kernel_launch(void* const* d_in, const int* in_sizes, int n_in,
                              void* d_out, int out_size)
{
    const float* x      = (const float*)d_in[0];
    const float* wq_w   = (const float*)d_in[1];
    const float* wkv_w  = (const float*)d_in[2];
    const float* wout_w = (const float*)d_in[3];
    const float* wout_b = (const float*)d_in[4];
    const float* hq_w   = (const float*)d_in[5];
    const float* hkv_w  = (const float*)d_in[6];
    const float* hout_w = (const float*)d_in[7];
    const float* hout_b = (const float*)d_in[8];
    float* out = (float*)d_out;

    __nv_bfloat16 *xh, *xl, *Bph, *Bpl, *Ph, *Pl, *Ohi, *Olo, *Boh, *Bol;
    cudaGetSymbolAddress((void**)&xh, g_xh);
    cudaGetSymbolAddress((void**)&xl, g_xl);
    cudaGetSymbolAddress((void**)&Bph, g_Bph);
    cudaGetSymbolAddress((void**)&Bpl, g_Bpl);
    cudaGetSymbolAddress((void**)&Ph, g_Ph);
    cudaGetSymbolAddress((void**)&Pl, g_Pl);
    cudaGetSymbolAddress((void**)&Ohi, g_Ohi);
    cudaGetSymbolAddress((void**)&Olo, g_Olo);
    cudaGetSymbolAddress((void**)&Boh, g_Boh);
    cudaGetSymbolAddress((void**)&Bol, g_Bol);

    cudaFuncSetAttribute(gemm_mma, cudaFuncAttributeMaxDynamicSharedMemorySize, GEMM_SMEM);
    cudaFuncSetAttribute(attn_w_mma, cudaFuncAttributeMaxDynamicSharedMemorySize, ATTNW_SMEM);
    cudaFuncSetAttribute(dots_h_mma, cudaFuncAttributeMaxDynamicSharedMemorySize, DOTS_SMEM);
    cudaFuncSetAttribute(av_h_mma, cudaFuncAttributeMaxDynamicSharedMemorySize, AV_SMEM);

    // 1) splits + weight panels
    split_f32_kernel<<<4096, 256>>>(x, xh, xl, (size_t)NTOK * DIMD);
    build_Bp_kernel<<<3072, 256>>>(wq_w, wkv_w, hq_w, hkv_w);
    build_Bo_kernel<<<1024, 256>>>(wout_w, hout_w);

    // 2) projections -> P (bf16 hi/lo)
    gemm_mma<<<dim3(24, 256), 256, GEMM_SMEM>>>(xh, xl, DIMD, Bph, Bpl, DIMD,
                                                nullptr, Ph, Pl, PLD, DIMD,
                                                nullptr, nullptr);

    // 3) column attention (w branch) -> O cols [0,512)
    attn_w_mma<<<dim3(256, 8), 256, ATTNW_SMEM>>>();

    // 4) tied row attention (h branch) -> O cols [512,1024)
    dots_h_mma<<<dim3(4, 8, DSPLIT), 256, DOTS_SMEM>>>();
    softmax_h_kernel<<<2048, 256>>>();
    av_h_mma<<<dim3(128, 8), 256, AV_SMEM>>>();

    // 5) out = O @ [wout;hout] + biases
    gemm_mma<<<dim3(2, 256), 256, GEMM_SMEM>>>(Ohi, Olo, OLD, Boh, Bol, 1024,
                                               out, nullptr, nullptr, DIMD, 1024,
                                               wout_b, hout_b);
}

// round 14
// speedup vs baseline: 1.2275x; 1.1368x over previous
#include <cuda_runtime.h>
#include <cuda_bf16.h>
#include <cuda_fp16.h>
#include <cstdint>

#define NTOK  32768
#define DIMD  256
#define HEADS 8
#define MSAH  128
#define MSAW  256
#define PLD   3072   // P cols: [wq(512) | wk@512 | wv@1024 | hq@1536 | hk@2048 | hv@2560]
#define OLD   1024   // O cols: [Ow(512) | Oh(512)]
#define TSC   0.011048543456039806f  // 64^-0.5 * 128^-0.5
#define DSPLIT 8     // dots_h split-K factor

// ---------------------------------------------------------------------------
// Scratch
// ---------------------------------------------------------------------------
__device__ __nv_bfloat16 g_Ph[(size_t)NTOK * PLD];
__device__ __nv_bfloat16 g_Pl[(size_t)NTOK * PLD];
__device__ float g_Shp[DSPLIT * HEADS * 256 * 256];
__device__ __nv_bfloat16 g_Shh[HEADS * 256 * 256];
__device__ __nv_bfloat16 g_Shl[HEADS * 256 * 256];
__device__ __half g_x16h[(size_t)NTOK * DIMD];        // x exact fp16 hi/lo split
__device__ __half g_x16l[(size_t)NTOK * DIMD];
__device__ __half g_Bp16[3072 * 256];                 // proj weights, [N][K] fp16
__device__ __nv_bfloat16 g_Ohi[(size_t)NTOK * OLD];
__device__ __nv_bfloat16 g_Olo[(size_t)NTOK * OLD];
__device__ __nv_bfloat16 g_Boh[256 * 1024];
__device__ __nv_bfloat16 g_Bol[256 * 1024];

// ---------------------------------------------------------------------------
// PTX helpers (compute_103-safe)
// ---------------------------------------------------------------------------
__device__ __forceinline__ uint32_t smem_to_u32(const void* p) {
    uint32_t a;
    asm("{ .reg .u64 t; cvta.to.shared.u64 t, %1; cvt.u32.u64 %0, t; }" : "=r"(a) : "l"(p));
    return a;
}
#define CP_ASYNC16(dst, src) \
    asm volatile("cp.async.cg.shared.global [%0], [%1], 16;" :: "r"(dst), "l"(src) : "memory")
#define CP_COMMIT() asm volatile("cp.async.commit_group;" ::: "memory")
#define CP_WAIT0()  asm volatile("cp.async.wait_group 0;" ::: "memory")
#define CP_WAIT1()  asm volatile("cp.async.wait_group 1;" ::: "memory")

#define LDMATRIX_X4(d0, d1, d2, d3, addr) \
    asm volatile("ldmatrix.sync.aligned.m8n8.x4.shared.b16 {%0,%1,%2,%3}, [%4];" \
        : "=r"(d0), "=r"(d1), "=r"(d2), "=r"(d3) : "r"(addr))
#define LDMATRIX_X4_T(d0, d1, d2, d3, addr) \
    asm volatile("ldmatrix.sync.aligned.m8n8.x4.trans.shared.b16 {%0,%1,%2,%3}, [%4];" \
        : "=r"(d0), "=r"(d1), "=r"(d2), "=r"(d3) : "r"(addr))

#define MMA_BF16(c, a0, a1, a2, a3, b0, b1) \
    asm volatile("mma.sync.aligned.m16n8k16.row.col.f32.bf16.bf16.f32 " \
        "{%0,%1,%2,%3}, {%4,%5,%6,%7}, {%8,%9}, {%0,%1,%2,%3};" \
        : "+f"((c)[0]), "+f"((c)[1]), "+f"((c)[2]), "+f"((c)[3]) \
        : "r"(a0), "r"(a1), "r"(a2), "r"(a3), "r"(b0), "r"(b1))

#define MMA_F16(c, a0, a1, a2, a3, b0, b1) \
    asm volatile("mma.sync.aligned.m16n8k16.row.col.f32.f16.f16.f32 " \
        "{%0,%1,%2,%3}, {%4,%5,%6,%7}, {%8,%9}, {%0,%1,%2,%3};" \
        : "+f"((c)[0]), "+f"((c)[1]), "+f"((c)[2]), "+f"((c)[3]) \
        : "r"(a0), "r"(a1), "r"(a2), "r"(a3), "r"(b0), "r"(b1))

__device__ __forceinline__ uint32_t pack_bf16x2(float lo, float hi) {
    __nv_bfloat162 t = __floats2bfloat162_rn(lo, hi);
    return *reinterpret_cast<uint32_t*>(&t);
}
__device__ __forceinline__ void split2_store(__nv_bfloat16* hi, __nv_bfloat16* lo,
                                             float a, float b) {
    __nv_bfloat16 ha = __float2bfloat16(a), hb = __float2bfloat16(b);
    __nv_bfloat162 h; h.x = ha; h.y = hb;
    *reinterpret_cast<__nv_bfloat162*>(hi) = h;
    __nv_bfloat162 l;
    l.x = __float2bfloat16(a - __bfloat162float(ha));
    l.y = __float2bfloat16(b - __bfloat162float(hb));
    *reinterpret_cast<__nv_bfloat162*>(lo) = l;
}

// ---------------------------------------------------------------------------
// 128x128 tile compute (bf16 3-term; dots_h + out-gemm).
// ---------------------------------------------------------------------------
__device__ __forceinline__ void compute_chunk128(uint32_t sAst, uint32_t sBst,
                                                 int lane, int wm, int wn,
                                                 float acc[2][8][4])
{
#pragma unroll
    for (int kb = 0; kb < 2; kb++) {
        const int lg = kb * 2 + (lane >> 4);
        uint32_t ah[2][4], al[2][4];
#pragma unroll
        for (int mi = 0; mi < 2; mi++) {
            const int row = wm * 32 + mi * 16 + (lane & 15);
            LDMATRIX_X4(ah[mi][0], ah[mi][1], ah[mi][2], ah[mi][3],
                        sAst + row * 128 + (((lg) ^ (row & 7)) << 4));
            LDMATRIX_X4(al[mi][0], al[mi][1], al[mi][2], al[mi][3],
                        sAst + row * 128 + (((lg + 4) ^ (row & 7)) << 4));
        }
        uint32_t b[4][4];
#pragma unroll
        for (int nf = 0; nf < 4; nf++) {
            const int row = wn * 64 + nf * 16 + (lane & 15);
            LDMATRIX_X4(b[nf][0], b[nf][1], b[nf][2], b[nf][3],
                        sBst + row * 128 + (((lg) ^ (row & 7)) << 4));
        }
#pragma unroll
        for (int nf = 0; nf < 4; nf++)
#pragma unroll
            for (int mi = 0; mi < 2; mi++) {
                MMA_BF16(acc[mi][2 * nf],     ah[mi][0], ah[mi][1], ah[mi][2], ah[mi][3], b[nf][0], b[nf][2]);
                MMA_BF16(acc[mi][2 * nf + 1], ah[mi][0], ah[mi][1], ah[mi][2], ah[mi][3], b[nf][1], b[nf][3]);
            }
#pragma unroll
        for (int nf = 0; nf < 4; nf++)
#pragma unroll
            for (int mi = 0; mi < 2; mi++) {
                MMA_BF16(acc[mi][2 * nf],     al[mi][0], al[mi][1], al[mi][2], al[mi][3], b[nf][0], b[nf][2]);
                MMA_BF16(acc[mi][2 * nf + 1], al[mi][0], al[mi][1], al[mi][2], al[mi][3], b[nf][1], b[nf][3]);
            }
#pragma unroll
        for (int nf = 0; nf < 4; nf++) {
            const int row = wn * 64 + nf * 16 + (lane & 15);
            LDMATRIX_X4(b[nf][0], b[nf][1], b[nf][2], b[nf][3],
                        sBst + row * 128 + (((lg + 4) ^ (row & 7)) << 4));
        }
#pragma unroll
        for (int nf = 0; nf < 4; nf++)
#pragma unroll
            for (int mi = 0; mi < 2; mi++) {
                MMA_BF16(acc[mi][2 * nf],     ah[mi][0], ah[mi][1], ah[mi][2], ah[mi][3], b[nf][0], b[nf][2]);
                MMA_BF16(acc[mi][2 * nf + 1], ah[mi][0], ah[mi][1], ah[mi][2], ah[mi][3], b[nf][1], b[nf][3]);
            }
    }
}

// ---------------------------------------------------------------------------
// Projection GEMM: fp16 2-term. A = x (exact fp16 hi+lo), B = W (single fp16).
// C = Ah@B^T + Al@B^T, emitted as bf16 hi/lo split.
// Tile 128x128, 2 CTAs/SM. Stage: A 16KB (gran 0-3 hi, 4-7 lo) + B 16KB (gran 0-3).
// ---------------------------------------------------------------------------
#define PROJ_SMEM (3 * 32768)

__global__ __launch_bounds__(256, 2)
void gemm_proj_f16(const __half* __restrict__ Ah, const __half* __restrict__ Al, int lda,
                   const __half* __restrict__ Bh, int ldb,
                   __nv_bfloat16* __restrict__ Chi, __nv_bfloat16* __restrict__ Clo,
                   int ldc, int K)
{
    extern __shared__ char smem[];
    const uint32_t sb = smem_to_u32(smem);
    const int tid = threadIdx.x, lane = tid & 31, wid = tid >> 5;
    const int wm = wid & 3, wn = wid >> 2;
    const int m0 = blockIdx.y * 128, j0 = blockIdx.x * 128;
    const int NC = K >> 5;

    float acc[2][8][4];
#pragma unroll
    for (int i = 0; i < 2; i++)
#pragma unroll
        for (int j = 0; j < 8; j++)
#pragma unroll
            for (int u = 0; u < 4; u++) acc[i][j][u] = 0.f;

    auto load_chunk = [&](int c, int s) {
        const int kc = c << 5;
        const uint32_t sA = sb + s * 32768, sB = sA + 16384;
        // A: 128 rows x 8 granules (0-3 hi, 4-7 lo)
#pragma unroll
        for (int i = 0; i < 4; i++) {
            const int id = tid + i * 256;
            const int row = id & 127, g = id >> 7;
            const uint32_t off = row * 128 + ((g ^ (row & 7)) << 4);
            const __half* Asrc = (g < 4) ? Ah : Al;
            CP_ASYNC16(sA + off, Asrc + (size_t)(m0 + row) * lda + kc + (g & 3) * 8);
        }
        // B: 128 rows x 4 granules (hi only)
#pragma unroll
        for (int i = 0; i < 2; i++) {
            const int id = tid + i * 256;
            const int row = id & 127, g = id >> 7;   // g in 0..3
            const uint32_t off = row * 128 + ((g ^ (row & 7)) << 4);
            CP_ASYNC16(sB + off, Bh + (size_t)(j0 + row) * ldb + kc + g * 8);
        }
        CP_COMMIT();
    };

    load_chunk(0, 0);
    load_chunk(1, 1);
    for (int c = 0; c < NC; c++) {
        if (c < NC - 1) { CP_WAIT1(); } else { CP_WAIT0(); }
        __syncthreads();
        if (c + 2 < NC) load_chunk(c + 2, (c + 2) % 3);
        const uint32_t sA = sb + (c % 3) * 32768, sB = sA + 16384;
#pragma unroll
        for (int kb = 0; kb < 2; kb++) {
            const int lg = kb * 2 + (lane >> 4);
            uint32_t ah[2][4], al[2][4];
#pragma unroll
            for (int mi = 0; mi < 2; mi++) {
                const int row = wm * 32 + mi * 16 + (lane & 15);
                LDMATRIX_X4(ah[mi][0], ah[mi][1], ah[mi][2], ah[mi][3],
                            sA + row * 128 + (((lg) ^ (row & 7)) << 4));
                LDMATRIX_X4(al[mi][0], al[mi][1], al[mi][2], al[mi][3],
                            sA + row * 128 + (((lg + 4) ^ (row & 7)) << 4));
            }
            uint32_t b[4][4];
#pragma unroll
            for (int nf = 0; nf < 4; nf++) {
                const int row = wn * 64 + nf * 16 + (lane & 15);
                LDMATRIX_X4(b[nf][0], b[nf][1], b[nf][2], b[nf][3],
                            sB + row * 128 + (((lg) ^ (row & 7)) << 4));
            }
            // pass 1: Ah * B
#pragma unroll
            for (int nf = 0; nf < 4; nf++)
#pragma unroll
                for (int mi = 0; mi < 2; mi++) {
                    MMA_F16(acc[mi][2 * nf],     ah[mi][0], ah[mi][1], ah[mi][2], ah[mi][3], b[nf][0], b[nf][2]);
                    MMA_F16(acc[mi][2 * nf + 1], ah[mi][0], ah[mi][1], ah[mi][2], ah[mi][3], b[nf][1], b[nf][3]);
                }
            // pass 2: Al * B
#pragma unroll
            for (int nf = 0; nf < 4; nf++)
#pragma unroll
                for (int mi = 0; mi < 2; mi++) {
                    MMA_F16(acc[mi][2 * nf],     al[mi][0], al[mi][1], al[mi][2], al[mi][3], b[nf][0], b[nf][2]);
                    MMA_F16(acc[mi][2 * nf + 1], al[mi][0], al[mi][1], al[mi][2], al[mi][3], b[nf][1], b[nf][3]);
                }
        }
    }

    const int qrow = lane >> 2, qcol2 = (lane & 3) * 2;
#pragma unroll
    for (int nj = 0; nj < 8; nj++) {
        const int n = j0 + wn * 64 + nj * 8 + qcol2;
#pragma unroll
        for (int mi = 0; mi < 2; mi++) {
            const int m = m0 + wm * 32 + mi * 16 + qrow;
            split2_store(Chi + (size_t)m * ldc + n, Clo + (size_t)m * ldc + n,
                         acc[mi][nj][0], acc[mi][nj][1]);
            split2_store(Chi + (size_t)(m + 8) * ldc + n, Clo + (size_t)(m + 8) * ldc + n,
                         acc[mi][nj][2], acc[mi][nj][3]);
        }
    }
}

// ---------------------------------------------------------------------------
// Fused hi/lo split-bf16 GEMM (out-projection). Tile 128x128, 2 CTAs/SM.
// ---------------------------------------------------------------------------
#define GEMM_SMEM (3 * 32768)

__global__ __launch_bounds__(256, 2)
void gemm_mma(const __nv_bfloat16* __restrict__ Ah, const __nv_bfloat16* __restrict__ Al, int lda,
              const __nv_bfloat16* __restrict__ Bh, const __nv_bfloat16* __restrict__ Bl, int ldb,
              float* __restrict__ C, int ldc, int K,
              const float* __restrict__ bias1, const float* __restrict__ bias2)
{
    extern __shared__ char smem[];
    const uint32_t sb = smem_to_u32(smem);
    const int tid = threadIdx.x, lane = tid & 31, wid = tid >> 5;
    const int wm = wid & 3, wn = wid >> 2;
    const int m0 = blockIdx.y * 128, j0 = blockIdx.x * 128;
    const int NC = K >> 5;

    float acc[2][8][4];
#pragma unroll
    for (int i = 0; i < 2; i++)
#pragma unroll
        for (int j = 0; j < 8; j++)
#pragma unroll
            for (int u = 0; u < 4; u++) acc[i][j][u] = 0.f;

    auto load_chunk = [&](int c, int s) {
        const int kc = c << 5;
        const uint32_t sA = sb + s * 32768, sB = sA + 16384;
#pragma unroll
        for (int i = 0; i < 4; i++) {
            const int id = tid + i * 256;
            const int row = id & 127, g = id >> 7;
            const uint32_t off = row * 128 + ((g ^ (row & 7)) << 4);
            const __nv_bfloat16* Asrc = (g < 4) ? Ah : Al;
            const __nv_bfloat16* Bsrc = (g < 4) ? Bh : Bl;
            CP_ASYNC16(sA + off, Asrc + (size_t)(m0 + row) * lda + kc + (g & 3) * 8);
            CP_ASYNC16(sB + off, Bsrc + (size_t)(j0 + row) * ldb + kc + (g & 3) * 8);
        }
        CP_COMMIT();
    };

    load_chunk(0, 0);
    load_chunk(1, 1);
    for (int c = 0; c < NC; c++) {
        if (c < NC - 1) { CP_WAIT1(); } else { CP_WAIT0(); }
        __syncthreads();
        if (c + 2 < NC) load_chunk(c + 2, (c + 2) % 3);
        const uint32_t sA = sb + (c % 3) * 32768;
        compute_chunk128(sA, sA + 16384, lane, wm, wn, acc);
    }

    const int qrow = lane >> 2, qcol2 = (lane & 3) * 2;
#pragma unroll
    for (int nj = 0; nj < 8; nj++) {
        const int n = j0 + wn * 64 + nj * 8 + qcol2;
        float b0 = bias1[n] + bias2[n];
        float b1 = bias1[n + 1] + bias2[n + 1];
#pragma unroll
        for (int mi = 0; mi < 2; mi++) {
            const int m = m0 + wm * 32 + mi * 16 + qrow;
            float2 v0, v1;
            v0.x = acc[mi][nj][0] + b0; v0.y = acc[mi][nj][1] + b1;
            v1.x = acc[mi][nj][2] + b0; v1.y = acc[mi][nj][3] + b1;
            *(float2*)(C + (size_t)m * ldc + n) = v0;
            *(float2*)(C + (size_t)(m + 8) * ldc + n) = v1;
        }
    }
}

// ---------------------------------------------------------------------------
// splitters / weight-panel builders
// ---------------------------------------------------------------------------
__global__ void split_f16_kernel(const float* __restrict__ in,
                                 __half* __restrict__ hi,
                                 __half* __restrict__ lo, size_t n)
{
    size_t i = (size_t)blockIdx.x * blockDim.x + threadIdx.x;
    const size_t stride = (size_t)gridDim.x * blockDim.x;
    for (; i < n; i += stride) {
        float v = in[i];
        __half h = __float2half_rn(v);
        hi[i] = h;
        lo[i] = __float2half_rn(v - __half2float(h));
    }
}
__global__ void build_Bp_kernel(const float* __restrict__ wq, const float* __restrict__ wkv,
                                const float* __restrict__ hq, const float* __restrict__ hkv)
{
    const int idx = blockIdx.x * 256 + threadIdx.x;   // k*3072 + n
    const int k = idx / 3072, n = idx - k * 3072;
    float v;
    if (n < 512)       v = wq[k * 512 + n];
    else if (n < 1536) v = wkv[k * 1024 + (n - 512)];
    else if (n < 2048) v = hq[k * 512 + (n - 1536)];
    else               v = hkv[k * 1024 + (n - 2048)];
    g_Bp16[(size_t)n * 256 + k] = __float2half_rn(v);
}
__global__ void build_Bo_kernel(const float* __restrict__ wo, const float* __restrict__ ho)
{
    const int idx = blockIdx.x * 256 + threadIdx.x;   // k*256 + n
    const int k = idx >> 8, n = idx & 255;
    float v = (k < 512) ? wo[k * 256 + n] : ho[(k - 512) * 256 + n];
    __nv_bfloat16 h = __float2bfloat16(v);
    g_Boh[(size_t)n * 1024 + k] = h;
    g_Bol[(size_t)n * 1024 + k] = __float2bfloat16(v - __bfloat162float(h));
}

// ---------------------------------------------------------------------------
// Column attention (w branch). One block per (cw, H). bf16 3-term.
// ---------------------------------------------------------------------------
#define ATTNW_SMEM (6 * 16384)

__global__ __launch_bounds__(256) void attn_w_mma()
{
    extern __shared__ char smem[];
    const uint32_t sb = smem_to_u32(smem);
    const int cw = blockIdx.x, H = blockIdx.y;
    const int tid = threadIdx.x, lane = tid & 31, wid = tid >> 5;

#pragma unroll
    for (int t = 0; t < 6; t++) {
        const __nv_bfloat16* src = (t & 1) ? g_Pl : g_Ph;
        const int coff = (t >> 1) * 512 + H * 64;
#pragma unroll
        for (int i = 0; i < 4; i++) {
            const int id = tid + i * 256;
            const int row = id & 127, g = id >> 7;
            CP_ASYNC16(sb + t * 16384 + row * 128 + ((g ^ (row & 7)) << 4),
                       src + (size_t)(row * 256 + cw) * PLD + coff + g * 8);
        }
    }
    CP_COMMIT(); CP_WAIT0();
    __syncthreads();

    const uint32_t sQh = sb, sQl = sb + 16384, sKh = sb + 32768,
                   sKl = sb + 49152, sVh = sb + 65536, sVl = sb + 81920;
    const int i0w = wid * 16;

    float acc[16][4];
#pragma unroll
    for (int i = 0; i < 16; i++)
#pragma unroll
        for (int u = 0; u < 4; u++) acc[i][u] = 0.f;

#pragma unroll
    for (int kb = 0; kb < 4; kb++) {
        const int lg = kb * 2 + (lane >> 4);
        const int ar = i0w + (lane & 15);
        const uint32_t aoff = ar * 128 + ((lg ^ (ar & 7)) << 4);
        uint32_t ah[4], al[4];
        LDMATRIX_X4(ah[0], ah[1], ah[2], ah[3], sQh + aoff);
        LDMATRIX_X4(al[0], al[1], al[2], al[3], sQl + aoff);
        uint32_t b[8][4];
#pragma unroll
        for (int nf = 0; nf < 8; nf++) {
            const int br = nf * 16 + (lane & 15);
            LDMATRIX_X4(b[nf][0], b[nf][1], b[nf][2], b[nf][3],
                        sKh + br * 128 + ((lg ^ (br & 7)) << 4));
        }
#pragma unroll
        for (int nf = 0; nf < 8; nf++) {
            MMA_BF16(acc[2 * nf],     ah[0], ah[1], ah[2], ah[3], b[nf][0], b[nf][2]);
            MMA_BF16(acc[2 * nf + 1], ah[0], ah[1], ah[2], ah[3], b[nf][1], b[nf][3]);
        }
#pragma unroll
        for (int nf = 0; nf < 8; nf++) {
            MMA_BF16(acc[2 * nf],     al[0], al[1], al[2], al[3], b[nf][0], b[nf][2]);
            MMA_BF16(acc[2 * nf + 1], al[0], al[1], al[2], al[3], b[nf][1], b[nf][3]);
        }
#pragma unroll
        for (int nf = 0; nf < 8; nf++) {
            const int br = nf * 16 + (lane & 15);
            LDMATRIX_X4(b[nf][0], b[nf][1], b[nf][2], b[nf][3],
                        sKl + br * 128 + ((lg ^ (br & 7)) << 4));
        }
#pragma unroll
        for (int nf = 0; nf < 8; nf++) {
            MMA_BF16(acc[2 * nf],     ah[0], ah[1], ah[2], ah[3], b[nf][0], b[nf][2]);
            MMA_BF16(acc[2 * nf + 1], ah[0], ah[1], ah[2], ah[3], b[nf][1], b[nf][3]);
        }
    }

    float mx0 = -1e30f, mx1 = -1e30f;
#pragma unroll
    for (int ni = 0; ni < 16; ni++) {
        acc[ni][0] *= 0.125f; acc[ni][1] *= 0.125f;
        acc[ni][2] *= 0.125f; acc[ni][3] *= 0.125f;
        mx0 = fmaxf(mx0, fmaxf(acc[ni][0], acc[ni][1]));
        mx1 = fmaxf(mx1, fmaxf(acc[ni][2], acc[ni][3]));
    }
    mx0 = fmaxf(mx0, __shfl_xor_sync(0xffffffffu, mx0, 1));
    mx0 = fmaxf(mx0, __shfl_xor_sync(0xffffffffu, mx0, 2));
    mx1 = fmaxf(mx1, __shfl_xor_sync(0xffffffffu, mx1, 1));
    mx1 = fmaxf(mx1, __shfl_xor_sync(0xffffffffu, mx1, 2));
    float s0 = 0.f, s1 = 0.f;
#pragma unroll
    for (int ni = 0; ni < 16; ni++) {
        float e;
        e = __expf(acc[ni][0] - mx0); acc[ni][0] = e; s0 += e;
        e = __expf(acc[ni][1] - mx0); acc[ni][1] = e; s0 += e;
        e = __expf(acc[ni][2] - mx1); acc[ni][2] = e; s1 += e;
        e = __expf(acc[ni][3] - mx1); acc[ni][3] = e; s1 += e;
    }
    s0 += __shfl_xor_sync(0xffffffffu, s0, 1);
    s0 += __shfl_xor_sync(0xffffffffu, s0, 2);
    s1 += __shfl_xor_sync(0xffffffffu, s1, 1);
    s1 += __shfl_xor_sync(0xffffffffu, s1, 2);
    const float inv0 = 1.f / s0, inv1 = 1.f / s1;

    uint32_t aph[8][4], apl[8][4];
#pragma unroll
    for (int kb = 0; kb < 8; kb++) {
        const int n0 = 2 * kb, n1 = n0 + 1;
        float p[8];
        p[0] = acc[n0][0] * inv0; p[1] = acc[n0][1] * inv0;
        p[2] = acc[n0][2] * inv1; p[3] = acc[n0][3] * inv1;
        p[4] = acc[n1][0] * inv0; p[5] = acc[n1][1] * inv0;
        p[6] = acc[n1][2] * inv1; p[7] = acc[n1][3] * inv1;
#pragma unroll
        for (int u = 0; u < 4; u++) {
            float a = p[2 * u], b = p[2 * u + 1];
            __nv_bfloat16 ha = __float2bfloat16(a), hb = __float2bfloat16(b);
            __nv_bfloat162 hh; hh.x = ha; hh.y = hb;
            aph[kb][u] = *reinterpret_cast<uint32_t*>(&hh);
            apl[kb][u] = pack_bf16x2(a - __bfloat162float(ha), b - __bfloat162float(hb));
        }
    }

    float acco[8][4];
#pragma unroll
    for (int i = 0; i < 8; i++)
#pragma unroll
        for (int u = 0; u < 4; u++) acco[i][u] = 0.f;

#pragma unroll
    for (int kb = 0; kb < 8; kb++) {
        const int jrow = kb * 16 + ((lane >> 3) & 1) * 8 + (lane & 7);
        uint32_t vb[4][4];
#pragma unroll
        for (int nfp = 0; nfp < 4; nfp++) {
            const int ncol = nfp * 16 + (lane >> 4) * 8;
            LDMATRIX_X4_T(vb[nfp][0], vb[nfp][1], vb[nfp][2], vb[nfp][3],
                          sVh + jrow * 128 + ((((ncol >> 3) ^ (jrow & 7))) << 4));
        }
#pragma unroll
        for (int nfp = 0; nfp < 4; nfp++) {
            MMA_BF16(acco[2 * nfp],     aph[kb][0], aph[kb][1], aph[kb][2], aph[kb][3], vb[nfp][0], vb[nfp][1]);
            MMA_BF16(acco[2 * nfp + 1], aph[kb][0], aph[kb][1], aph[kb][2], aph[kb][3], vb[nfp][2], vb[nfp][3]);
        }
#pragma unroll
        for (int nfp = 0; nfp < 4; nfp++) {
            MMA_BF16(acco[2 * nfp],     apl[kb][0], apl[kb][1], apl[kb][2], apl[kb][3], vb[nfp][0], vb[nfp][1]);
            MMA_BF16(acco[2 * nfp + 1], apl[kb][0], apl[kb][1], apl[kb][2], apl[kb][3], vb[nfp][2], vb[nfp][3]);
        }
#pragma unroll
        for (int nfp = 0; nfp < 4; nfp++) {
            const int ncol = nfp * 16 + (lane >> 4) * 8;
            LDMATRIX_X4_T(vb[nfp][0], vb[nfp][1], vb[nfp][2], vb[nfp][3],
                          sVl + jrow * 128 + ((((ncol >> 3) ^ (jrow & 7))) << 4));
        }
#pragma unroll
        for (int nfp = 0; nfp < 4; nfp++) {
            MMA_BF16(acco[2 * nfp],     aph[kb][0], aph[kb][1], aph[kb][2], aph[kb][3], vb[nfp][0], vb[nfp][1]);
            MMA_BF16(acco[2 * nfp + 1], aph[kb][0], aph[kb][1], aph[kb][2], aph[kb][3], vb[nfp][2], vb[nfp][3]);
        }
    }

    const int r0 = i0w + (lane >> 2), r1 = r0 + 8;
#pragma unroll
    for (int nf = 0; nf < 8; nf++) {
        const int c = H * 64 + nf * 8 + (lane & 3) * 2;
        const size_t t0 = (size_t)(r0 * 256 + cw) * OLD + c;
        const size_t t1 = (size_t)(r1 * 256 + cw) * OLD + c;
        split2_store(g_Ohi + t0, g_Olo + t0, acco[nf][0], acco[nf][1]);
        split2_store(g_Ohi + t1, g_Olo + t1, acco[nf][2], acco[nf][3]);
    }
}

// ---------------------------------------------------------------------------
// Tied row attention dots: split-K over r, DSPLIT=8.
// ---------------------------------------------------------------------------
#define DOTS_SMEM (3 * 32768)

__global__ __launch_bounds__(256, 2) void dots_h_mma()
{
    extern __shared__ char smem[];
    const uint32_t sb = smem_to_u32(smem);
    const int tid = threadIdx.x, lane = tid & 31, wid = tid >> 5;
    const int wm = wid & 3, wn = wid >> 2;
    const int i0 = (blockIdx.x & 1) * 128, j0 = (blockIdx.x >> 1) * 128;
    const int H = blockIdx.y, sp = blockIdx.z;
    const int rbase = sp * (128 / DSPLIT);
    const int NC = (128 / DSPLIT) * 2;

    float acc[2][8][4];
#pragma unroll
    for (int i = 0; i < 2; i++)
#pragma unroll
        for (int j = 0; j < 8; j++)
#pragma unroll
            for (int u = 0; u < 4; u++) acc[i][j][u] = 0.f;

    auto load_chunk = [&](int c, int s) {
        const int r = rbase + (c >> 1), dhc = (c & 1) * 32;
        const size_t abase = ((size_t)(r * 256 + i0)) * PLD + 1536 + H * 64 + dhc;
        const size_t bbase = ((size_t)(r * 256 + j0)) * PLD + 2048 + H * 64 + dhc;
        const uint32_t sA = sb + s * 32768, sB = sA + 16384;
#pragma unroll
        for (int i = 0; i < 4; i++) {
            const int id = tid + i * 256;
            const int row = id & 127, g = id >> 7;
            const uint32_t off = row * 128 + ((g ^ (row & 7)) << 4);
            const __nv_bfloat16* src = (g < 4) ? g_Ph : g_Pl;
            CP_ASYNC16(sA + off, src + abase + (size_t)row * PLD + (g & 3) * 8);
            CP_ASYNC16(sB + off, src + bbase + (size_t)row * PLD + (g & 3) * 8);
        }
        CP_COMMIT();
    };

    load_chunk(0, 0);
    load_chunk(1, 1);
    for (int c = 0; c < NC; c++) {
        if (c < NC - 1) { CP_WAIT1(); } else { CP_WAIT0(); }
        __syncthreads();
        if (c + 2 < NC) load_chunk(c + 2, (c + 2) % 3);
        const uint32_t sA = sb + (c % 3) * 32768;
        compute_chunk128(sA, sA + 16384, lane, wm, wn, acc);
    }

    float* Cp = g_Shp + (size_t)sp * 524288 + (size_t)H * 65536;
    const int qrow = lane >> 2, qcol2 = (lane & 3) * 2;
#pragma unroll
    for (int nj = 0; nj < 8; nj++) {
        const int n = j0 + wn * 64 + nj * 8 + qcol2;
#pragma unroll
        for (int mi = 0; mi < 2; mi++) {
            const int m = i0 + wm * 32 + mi * 16 + qrow;
            float2 v0, v1;
            v0.x = acc[mi][nj][0]; v0.y = acc[mi][nj][1];
            v1.x = acc[mi][nj][2]; v1.y = acc[mi][nj][3];
            *(float2*)(Cp + m * 256 + n) = v0;
            *(float2*)(Cp + (m + 8) * 256 + n) = v1;
        }
    }
}

// Sum DSPLIT partials, scale, softmax over 256, emit bf16 hi/lo probs.
__global__ __launch_bounds__(256) void softmax_h_kernel()
{
    const size_t base = (size_t)blockIdx.x * 256;
    const int t = threadIdx.x;
    __shared__ float red[256];
    float v = 0.f;
#pragma unroll
    for (int sp = 0; sp < DSPLIT; sp++)
        v += g_Shp[(size_t)sp * 524288 + base + t];
    v *= TSC;
    red[t] = v;
    __syncthreads();
#pragma unroll
    for (int s = 128; s > 0; s >>= 1) {
        if (t < s) red[t] = fmaxf(red[t], red[t + s]);
        __syncthreads();
    }
    const float m = red[0];
    __syncthreads();
    const float e = __expf(v - m);
    red[t] = e;
    __syncthreads();
#pragma unroll
    for (int s = 128; s > 0; s >>= 1) {
        if (t < s) red[t] += red[t + s];
        __syncthreads();
    }
    const float p = e / red[0];
    const __nv_bfloat16 h = __float2bfloat16(p);
    g_Shh[base + t] = h;
    g_Shl[base + t] = __float2bfloat16(p - __bfloat162float(h));
}

// ---------------------------------------------------------------------------
// Tied row attention AV. 2 CTAs/SM.
// ---------------------------------------------------------------------------
#define AV_SMEM (2 * 40960)   // 80 KB

__global__ __launch_bounds__(256, 2) void av_h_mma()
{
    extern __shared__ char smem[];
    const uint32_t sb = smem_to_u32(smem);
    const int r = blockIdx.x, H = blockIdx.y;
    const int tid = threadIdx.x, lane = tid & 31, wid = tid >> 5;
    const int i0w = wid * 32;
    const int NC = 8;

    float acc[2][8][4];
#pragma unroll
    for (int i = 0; i < 2; i++)
#pragma unroll
        for (int j = 0; j < 8; j++)
#pragma unroll
            for (int u = 0; u < 4; u++) acc[i][j][u] = 0.f;

    auto load_chunk = [&](int c, int s) {
        const int jc = c << 5;
        const uint32_t sA = sb + s * 40960, sV = sA + 32768;
#pragma unroll
        for (int i = 0; i < 8; i++) {
            const int id = tid + i * 256;
            const int row = id & 255, g = id >> 8;
            const __nv_bfloat16* src = (g < 4) ? g_Shh : g_Shl;
            CP_ASYNC16(sA + row * 128 + ((g ^ (row & 7)) << 4),
                       src + (size_t)H * 65536 + row * 256 + jc + (g & 3) * 8);
        }
#pragma unroll
        for (int i = 0; i < 2; i++) {
            const int id = tid + i * 256;
            const int jrow = id & 31, g = (id >> 5) & 7, half = id >> 8;
            const __nv_bfloat16* src = half ? g_Pl : g_Ph;
            CP_ASYNC16(sV + half * 4096 + jrow * 128 + ((g ^ (jrow & 7)) << 4),
                       src + (size_t)(r * 256 + jc + jrow) * PLD + 2560 + H * 64 + g * 8);
        }
        CP_COMMIT();
    };

    load_chunk(0, 0);
    load_chunk(1, 1);
    for (int c = 0; c < NC; c++) {
        if (c + 1 < NC) { CP_WAIT1(); } else { CP_WAIT0(); }
        __syncthreads();
        const uint32_t sA = sb + (c & 1) * 40960, sV = sA + 32768;
#pragma unroll
        for (int kb = 0; kb < 2; kb++) {
            const int lg = kb * 2 + (lane >> 4);
            uint32_t ah[2][4], al[2][4];
#pragma unroll
            for (int mi = 0; mi < 2; mi++) {
                const int row = i0w + mi * 16 + (lane & 15);
                LDMATRIX_X4(ah[mi][0], ah[mi][1], ah[mi][2], ah[mi][3],
                            sA + row * 128 + ((lg ^ (row & 7)) << 4));
                LDMATRIX_X4(al[mi][0], al[mi][1], al[mi][2], al[mi][3],
                            sA + row * 128 + (((lg + 4) ^ (row & 7)) << 4));
            }
            const int jrow = kb * 16 + ((lane >> 3) & 1) * 8 + (lane & 7);
            uint32_t vb[4][4];
#pragma unroll
            for (int nfp = 0; nfp < 4; nfp++) {
                const int ncol = nfp * 16 + (lane >> 4) * 8;
                LDMATRIX_X4_T(vb[nfp][0], vb[nfp][1], vb[nfp][2], vb[nfp][3],
                              sV + jrow * 128 + ((((ncol >> 3) ^ (jrow & 7))) << 4));
            }
#pragma unroll
            for (int nfp = 0; nfp < 4; nfp++)
#pragma unroll
                for (int mi = 0; mi < 2; mi++) {
                    MMA_BF16(acc[mi][2 * nfp],     ah[mi][0], ah[mi][1], ah[mi][2], ah[mi][3], vb[nfp][0], vb[nfp][1]);
                    MMA_BF16(acc[mi][2 * nfp + 1], ah[mi][0], ah[mi][1], ah[mi][2], ah[mi][3], vb[nfp][2], vb[nfp][3]);
                }
#pragma unroll
            for (int nfp = 0; nfp < 4; nfp++)
#pragma unroll
                for (int mi = 0; mi < 2; mi++) {
                    MMA_BF16(acc[mi][2 * nfp],     al[mi][0], al[mi][1], al[mi][2], al[mi][3], vb[nfp][0], vb[nfp][1]);
                    MMA_BF16(acc[mi][2 * nfp + 1], al[mi][0], al[mi][1], al[mi][2], al[mi][3], vb[nfp][2], vb[nfp][3]);
                }
#pragma unroll
            for (int nfp = 0; nfp < 4; nfp++) {
                const int ncol = nfp * 16 + (lane >> 4) * 8;
                LDMATRIX_X4_T(vb[nfp][0], vb[nfp][1], vb[nfp][2], vb[nfp][3],
                              sV + 4096 + jrow * 128 + ((((ncol >> 3) ^ (jrow & 7))) << 4));
            }
#pragma unroll
            for (int nfp = 0; nfp < 4; nfp++)
#pragma unroll
                for (int mi = 0; mi < 2; mi++) {
                    MMA_BF16(acc[mi][2 * nfp],     ah[mi][0], ah[mi][1], ah[mi][2], ah[mi][3], vb[nfp][0], vb[nfp][1]);
                    MMA_BF16(acc[mi][2 * nfp + 1], ah[mi][0], ah[mi][1], ah[mi][2], ah[mi][3], vb[nfp][2], vb[nfp][3]);
                }
        }
        __syncthreads();
        if (c + 2 < NC) load_chunk(c + 2, c & 1);
    }

    const int qrow = lane >> 2, qcol2 = (lane & 3) * 2;
#pragma unroll
    for (int nf = 0; nf < 8; nf++) {
        const int c = 512 + H * 64 + nf * 8 + qcol2;
#pragma unroll
        for (int mi = 0; mi < 2; mi++) {
            const int i = i0w + mi * 16 + qrow;
            const size_t t0 = (size_t)(r * 256 + i) * OLD + c;
            const size_t t1 = (size_t)(r * 256 + i + 8) * OLD + c;
            split2_store(g_Ohi + t0, g_Olo + t0, acc[mi][nf][0], acc[mi][nf][1]);
            split2_store(g_Ohi + t1, g_Olo + t1, acc[mi][nf][2], acc[mi][nf][3]);
        }
    }
}

// ---------------------------------------------------------------------------
extern "C" void kernel_launch(void* const* d_in, const int* in_sizes, int n_in,
                              void* d_out, int out_size)
{
    const float* x      = (const float*)d_in[0];
    const float* wq_w   = (const float*)d_in[1];
    const float* wkv_w  = (const float*)d_in[2];
    const float* wout_w = (const float*)d_in[3];
    const float* wout_b = (const float*)d_in[4];
    const float* hq_w   = (const float*)d_in[5];
    const float* hkv_w  = (const float*)d_in[6];
    const float* hout_w = (const float*)d_in[7];
    const float* hout_b = (const float*)d_in[8];
    float* out = (float*)d_out;

    __half *x16h, *x16l, *Bp16;
    __nv_bfloat16 *Ph, *Pl, *Ohi, *Olo, *Boh, *Bol;
    cudaGetSymbolAddress((void**)&x16h, g_x16h);
    cudaGetSymbolAddress((void**)&x16l, g_x16l);
    cudaGetSymbolAddress((void**)&Bp16, g_Bp16);
    cudaGetSymbolAddress((void**)&Ph, g_Ph);
    cudaGetSymbolAddress((void**)&Pl, g_Pl);
    cudaGetSymbolAddress((void**)&Ohi, g_Ohi);
    cudaGetSymbolAddress((void**)&Olo, g_Olo);
    cudaGetSymbolAddress((void**)&Boh, g_Boh);
    cudaGetSymbolAddress((void**)&Bol, g_Bol);

    cudaFuncSetAttribute(gemm_proj_f16, cudaFuncAttributeMaxDynamicSharedMemorySize, PROJ_SMEM);
    cudaFuncSetAttribute(gemm_mma, cudaFuncAttributeMaxDynamicSharedMemorySize, GEMM_SMEM);
    cudaFuncSetAttribute(attn_w_mma, cudaFuncAttributeMaxDynamicSharedMemorySize, ATTNW_SMEM);
    cudaFuncSetAttribute(dots_h_mma, cudaFuncAttributeMaxDynamicSharedMemorySize, DOTS_SMEM);
    cudaFuncSetAttribute(av_h_mma, cudaFuncAttributeMaxDynamicSharedMemorySize, AV_SMEM);

    // 1) splits + weight panels
    split_f16_kernel<<<4096, 256>>>(x, x16h, x16l, (size_t)NTOK * DIMD);
    build_Bp_kernel<<<3072, 256>>>(wq_w, wkv_w, hq_w, hkv_w);
    build_Bo_kernel<<<1024, 256>>>(wout_w, hout_w);

    // 2) projections -> P (bf16 hi/lo) via fp16 2-term GEMM
    gemm_proj_f16<<<dim3(24, 256), 256, PROJ_SMEM>>>(x16h, x16l, DIMD, Bp16, DIMD,
                                                     Ph, Pl, PLD, DIMD);

    // 3) column attention (w branch) -> O cols [0,512)
    attn_w_mma<<<dim3(256, 8), 256, ATTNW_SMEM>>>();

    // 4) tied row attention (h branch) -> O cols [512,1024)
    dots_h_mma<<<dim3(4, 8, DSPLIT), 256, DOTS_SMEM>>>();
    softmax_h_kernel<<<2048, 256>>>();
    av_h_mma<<<dim3(128, 8), 256, AV_SMEM>>>();

    // 5) out = O @ [wout;hout] + biases (bf16 3-term)
    gemm_mma<<<dim3(2, 256), 256, GEMM_SMEM>>>(Ohi, Olo, OLD, Boh, Bol, 1024,
                                               out, DIMD, 1024, wout_b, hout_b);
}

// round 15
// speedup vs baseline: 1.4383x; 1.1717x over previous
#include <cuda_runtime.h>
#include <cuda_bf16.h>
#include <cuda_fp16.h>
#include <cstdint>

#define NTOK  32768
#define DIMD  256
#define HEADS 8
#define MSAH  128
#define MSAW  256
#define PLD   3072   // P cols: [wq(512) | wk@512 | wv@1024 | hq@1536 | hk@2048 | hv@2560]
#define OLD   1024   // O cols: [Ow(512) | Oh(512)]
#define TSC   0.011048543456039806f  // 64^-0.5 * 128^-0.5
#define DSPLIT 8     // dots_h split-K factor

// ---------------------------------------------------------------------------
// Scratch (all fp16 hi/lo splits)
// ---------------------------------------------------------------------------
__device__ __half g_Ph[(size_t)NTOK * PLD];
__device__ __half g_Pl[(size_t)NTOK * PLD];
__device__ float g_Shp[DSPLIT * HEADS * 256 * 256];
__device__ __half g_Shh[HEADS * 256 * 256];
__device__ __half g_Shl[HEADS * 256 * 256];
__device__ __half g_x16h[(size_t)NTOK * DIMD];
__device__ __half g_x16l[(size_t)NTOK * DIMD];
__device__ __half g_Bp16[3072 * 256];
__device__ __half g_Ohi[(size_t)NTOK * OLD];
__device__ __half g_Olo[(size_t)NTOK * OLD];
__device__ __half g_Bo16[256 * 1024];

// ---------------------------------------------------------------------------
// PTX helpers (compute_103-safe)
// ---------------------------------------------------------------------------
__device__ __forceinline__ uint32_t smem_to_u32(const void* p) {
    uint32_t a;
    asm("{ .reg .u64 t; cvta.to.shared.u64 t, %1; cvt.u32.u64 %0, t; }" : "=r"(a) : "l"(p));
    return a;
}
#define CP_ASYNC16(dst, src) \
    asm volatile("cp.async.cg.shared.global [%0], [%1], 16;" :: "r"(dst), "l"(src) : "memory")
#define CP_COMMIT() asm volatile("cp.async.commit_group;" ::: "memory")
#define CP_WAIT0()  asm volatile("cp.async.wait_group 0;" ::: "memory")
#define CP_WAIT1()  asm volatile("cp.async.wait_group 1;" ::: "memory")

#define LDMATRIX_X4(d0, d1, d2, d3, addr) \
    asm volatile("ldmatrix.sync.aligned.m8n8.x4.shared.b16 {%0,%1,%2,%3}, [%4];" \
        : "=r"(d0), "=r"(d1), "=r"(d2), "=r"(d3) : "r"(addr))
#define LDMATRIX_X4_T(d0, d1, d2, d3, addr) \
    asm volatile("ldmatrix.sync.aligned.m8n8.x4.trans.shared.b16 {%0,%1,%2,%3}, [%4];" \
        : "=r"(d0), "=r"(d1), "=r"(d2), "=r"(d3) : "r"(addr))

#define MMA_F16(c, a0, a1, a2, a3, b0, b1) \
    asm volatile("mma.sync.aligned.m16n8k16.row.col.f32.f16.f16.f32 " \
        "{%0,%1,%2,%3}, {%4,%5,%6,%7}, {%8,%9}, {%0,%1,%2,%3};" \
        : "+f"((c)[0]), "+f"((c)[1]), "+f"((c)[2]), "+f"((c)[3]) \
        : "r"(a0), "r"(a1), "r"(a2), "r"(a3), "r"(b0), "r"(b1))

__device__ __forceinline__ uint32_t pack_h16x2(float a, float b) {
    __half2 t = __floats2half2_rn(a, b);
    return *reinterpret_cast<uint32_t*>(&t);
}
__device__ __forceinline__ void split2_store_f16(__half* hi, __half* lo, float a, float b) {
    __half ha = __float2half_rn(a), hb = __float2half_rn(b);
    __half2 h; h.x = ha; h.y = hb;
    *reinterpret_cast<__half2*>(hi) = h;
    __half2 l;
    l.x = __float2half_rn(a - __half2float(ha));
    l.y = __float2half_rn(b - __half2float(hb));
    *reinterpret_cast<__half2*>(lo) = l;
}

// ---------------------------------------------------------------------------
// Unified fp16 2-term GEMM: C = Ah@B^T + Al@B^T.
// A granules 0-3 hi / 4-7 lo (16KB); B granules 0-3 (8KB used of 16KB slot).
// Epilogue: fp32 C (+bias) if C != nullptr, else fp16 hi/lo split.
// Tile 128x128, 2 CTAs/SM.
// ---------------------------------------------------------------------------
#define GEMM_SMEM (3 * 32768)

__global__ __launch_bounds__(256, 2)
void gemm_f16(const __half* __restrict__ Ah, const __half* __restrict__ Al, int lda,
              const __half* __restrict__ B, int ldb,
              float* __restrict__ C, __half* __restrict__ Chi, __half* __restrict__ Clo,
              int ldc, int K,
              const float* __restrict__ bias1, const float* __restrict__ bias2)
{
    extern __shared__ char smem[];
    const uint32_t sb = smem_to_u32(smem);
    const int tid = threadIdx.x, lane = tid & 31, wid = tid >> 5;
    const int wm = wid & 3, wn = wid >> 2;
    const int m0 = blockIdx.y * 128, j0 = blockIdx.x * 128;
    const int NC = K >> 5;

    float acc[2][8][4];
#pragma unroll
    for (int i = 0; i < 2; i++)
#pragma unroll
        for (int j = 0; j < 8; j++)
#pragma unroll
            for (int u = 0; u < 4; u++) acc[i][j][u] = 0.f;

    auto load_chunk = [&](int c, int s) {
        const int kc = c << 5;
        const uint32_t sA = sb + s * 32768, sB = sA + 16384;
#pragma unroll
        for (int i = 0; i < 4; i++) {
            const int id = tid + i * 256;
            const int row = id & 127, g = id >> 7;
            const uint32_t off = row * 128 + ((g ^ (row & 7)) << 4);
            const __half* Asrc = (g < 4) ? Ah : Al;
            CP_ASYNC16(sA + off, Asrc + (size_t)(m0 + row) * lda + kc + (g & 3) * 8);
        }
#pragma unroll
        for (int i = 0; i < 2; i++) {
            const int id = tid + i * 256;
            const int row = id & 127, g = id >> 7;   // 0..3
            const uint32_t off = row * 128 + ((g ^ (row & 7)) << 4);
            CP_ASYNC16(sB + off, B + (size_t)(j0 + row) * ldb + kc + g * 8);
        }
        CP_COMMIT();
    };

    load_chunk(0, 0);
    load_chunk(1, 1);
    for (int c = 0; c < NC; c++) {
        if (c < NC - 1) { CP_WAIT1(); } else { CP_WAIT0(); }
        __syncthreads();
        if (c + 2 < NC) load_chunk(c + 2, (c + 2) % 3);
        const uint32_t sA = sb + (c % 3) * 32768, sB = sA + 16384;
#pragma unroll
        for (int kb = 0; kb < 2; kb++) {
            const int lg = kb * 2 + (lane >> 4);
            uint32_t ah[2][4], al[2][4];
#pragma unroll
            for (int mi = 0; mi < 2; mi++) {
                const int row = wm * 32 + mi * 16 + (lane & 15);
                LDMATRIX_X4(ah[mi][0], ah[mi][1], ah[mi][2], ah[mi][3],
                            sA + row * 128 + (((lg) ^ (row & 7)) << 4));
                LDMATRIX_X4(al[mi][0], al[mi][1], al[mi][2], al[mi][3],
                            sA + row * 128 + (((lg + 4) ^ (row & 7)) << 4));
            }
            uint32_t b[4][4];
#pragma unroll
            for (int nf = 0; nf < 4; nf++) {
                const int row = wn * 64 + nf * 16 + (lane & 15);
                LDMATRIX_X4(b[nf][0], b[nf][1], b[nf][2], b[nf][3],
                            sB + row * 128 + (((lg) ^ (row & 7)) << 4));
            }
#pragma unroll
            for (int nf = 0; nf < 4; nf++)
#pragma unroll
                for (int mi = 0; mi < 2; mi++) {
                    MMA_F16(acc[mi][2 * nf],     ah[mi][0], ah[mi][1], ah[mi][2], ah[mi][3], b[nf][0], b[nf][2]);
                    MMA_F16(acc[mi][2 * nf + 1], ah[mi][0], ah[mi][1], ah[mi][2], ah[mi][3], b[nf][1], b[nf][3]);
                }
#pragma unroll
            for (int nf = 0; nf < 4; nf++)
#pragma unroll
                for (int mi = 0; mi < 2; mi++) {
                    MMA_F16(acc[mi][2 * nf],     al[mi][0], al[mi][1], al[mi][2], al[mi][3], b[nf][0], b[nf][2]);
                    MMA_F16(acc[mi][2 * nf + 1], al[mi][0], al[mi][1], al[mi][2], al[mi][3], b[nf][1], b[nf][3]);
                }
        }
    }

    const int qrow = lane >> 2, qcol2 = (lane & 3) * 2;
    if (C) {
#pragma unroll
        for (int nj = 0; nj < 8; nj++) {
            const int n = j0 + wn * 64 + nj * 8 + qcol2;
            float b0 = bias1[n] + bias2[n];
            float b1 = bias1[n + 1] + bias2[n + 1];
#pragma unroll
            for (int mi = 0; mi < 2; mi++) {
                const int m = m0 + wm * 32 + mi * 16 + qrow;
                float2 v0, v1;
                v0.x = acc[mi][nj][0] + b0; v0.y = acc[mi][nj][1] + b1;
                v1.x = acc[mi][nj][2] + b0; v1.y = acc[mi][nj][3] + b1;
                *(float2*)(C + (size_t)m * ldc + n) = v0;
                *(float2*)(C + (size_t)(m + 8) * ldc + n) = v1;
            }
        }
    } else {
#pragma unroll
        for (int nj = 0; nj < 8; nj++) {
            const int n = j0 + wn * 64 + nj * 8 + qcol2;
#pragma unroll
            for (int mi = 0; mi < 2; mi++) {
                const int m = m0 + wm * 32 + mi * 16 + qrow;
                split2_store_f16(Chi + (size_t)m * ldc + n, Clo + (size_t)m * ldc + n,
                                 acc[mi][nj][0], acc[mi][nj][1]);
                split2_store_f16(Chi + (size_t)(m + 8) * ldc + n, Clo + (size_t)(m + 8) * ldc + n,
                                 acc[mi][nj][2], acc[mi][nj][3]);
            }
        }
    }
}

// ---------------------------------------------------------------------------
// splitters / weight-panel builders
// ---------------------------------------------------------------------------
__global__ void split_f16_kernel(const float* __restrict__ in,
                                 __half* __restrict__ hi,
                                 __half* __restrict__ lo, size_t n)
{
    size_t i = (size_t)blockIdx.x * blockDim.x + threadIdx.x;
    const size_t stride = (size_t)gridDim.x * blockDim.x;
    for (; i < n; i += stride) {
        float v = in[i];
        __half h = __float2half_rn(v);
        hi[i] = h;
        lo[i] = __float2half_rn(v - __half2float(h));
    }
}
__global__ void build_Bp_kernel(const float* __restrict__ wq, const float* __restrict__ wkv,
                                const float* __restrict__ hq, const float* __restrict__ hkv)
{
    const int idx = blockIdx.x * 256 + threadIdx.x;   // k*3072 + n
    const int k = idx / 3072, n = idx - k * 3072;
    float v;
    if (n < 512)       v = wq[k * 512 + n];
    else if (n < 1536) v = wkv[k * 1024 + (n - 512)];
    else if (n < 2048) v = hq[k * 512 + (n - 1536)];
    else               v = hkv[k * 1024 + (n - 2048)];
    g_Bp16[(size_t)n * 256 + k] = __float2half_rn(v);
}
__global__ void build_Bo_kernel(const float* __restrict__ wo, const float* __restrict__ ho)
{
    const int idx = blockIdx.x * 256 + threadIdx.x;   // k*256 + n
    const int k = idx >> 8, n = idx & 255;
    float v = (k < 512) ? wo[k * 256 + n] : ho[(k - 512) * 256 + n];
    g_Bo16[(size_t)n * 1024 + k] = __float2half_rn(v);
}

// ---------------------------------------------------------------------------
// Column attention (w branch), fp16 2-term. One block per (cw, H).
// Tiles: Qh Ql Kh Vh (4 x 16KB = 64KB).
// ---------------------------------------------------------------------------
#define ATTNW_SMEM (4 * 16384)

__global__ __launch_bounds__(256) void attn_w_mma()
{
    extern __shared__ char smem[];
    const uint32_t sb = smem_to_u32(smem);
    const int cw = blockIdx.x, H = blockIdx.y;
    const int tid = threadIdx.x, lane = tid & 31, wid = tid >> 5;

    // Tiles: 0=Qh, 1=Ql, 2=Kh, 3=Vh
    const __half* tsrc[4] = { g_Ph, g_Pl, g_Ph, g_Ph };
    const int tcoff[4] = { H * 64, H * 64, 512 + H * 64, 1024 + H * 64 };
#pragma unroll
    for (int t = 0; t < 4; t++) {
#pragma unroll
        for (int i = 0; i < 4; i++) {
            const int id = tid + i * 256;
            const int row = id & 127, g = id >> 7;
            CP_ASYNC16(sb + t * 16384 + row * 128 + ((g ^ (row & 7)) << 4),
                       tsrc[t] + (size_t)(row * 256 + cw) * PLD + tcoff[t] + g * 8);
        }
    }
    CP_COMMIT(); CP_WAIT0();
    __syncthreads();

    const uint32_t sQh = sb, sQl = sb + 16384, sKh = sb + 32768, sVh = sb + 49152;
    const int i0w = wid * 16;

    float acc[16][4];
#pragma unroll
    for (int i = 0; i < 16; i++)
#pragma unroll
        for (int u = 0; u < 4; u++) acc[i][u] = 0.f;

#pragma unroll
    for (int kb = 0; kb < 4; kb++) {
        const int lg = kb * 2 + (lane >> 4);
        const int ar = i0w + (lane & 15);
        const uint32_t aoff = ar * 128 + ((lg ^ (ar & 7)) << 4);
        uint32_t ah[4], al[4];
        LDMATRIX_X4(ah[0], ah[1], ah[2], ah[3], sQh + aoff);
        LDMATRIX_X4(al[0], al[1], al[2], al[3], sQl + aoff);
        uint32_t b[8][4];
#pragma unroll
        for (int nf = 0; nf < 8; nf++) {
            const int br = nf * 16 + (lane & 15);
            LDMATRIX_X4(b[nf][0], b[nf][1], b[nf][2], b[nf][3],
                        sKh + br * 128 + ((lg ^ (br & 7)) << 4));
        }
#pragma unroll
        for (int nf = 0; nf < 8; nf++) {
            MMA_F16(acc[2 * nf],     ah[0], ah[1], ah[2], ah[3], b[nf][0], b[nf][2]);
            MMA_F16(acc[2 * nf + 1], ah[0], ah[1], ah[2], ah[3], b[nf][1], b[nf][3]);
        }
#pragma unroll
        for (int nf = 0; nf < 8; nf++) {
            MMA_F16(acc[2 * nf],     al[0], al[1], al[2], al[3], b[nf][0], b[nf][2]);
            MMA_F16(acc[2 * nf + 1], al[0], al[1], al[2], al[3], b[nf][1], b[nf][3]);
        }
    }

    float mx0 = -1e30f, mx1 = -1e30f;
#pragma unroll
    for (int ni = 0; ni < 16; ni++) {
        acc[ni][0] *= 0.125f; acc[ni][1] *= 0.125f;
        acc[ni][2] *= 0.125f; acc[ni][3] *= 0.125f;
        mx0 = fmaxf(mx0, fmaxf(acc[ni][0], acc[ni][1]));
        mx1 = fmaxf(mx1, fmaxf(acc[ni][2], acc[ni][3]));
    }
    mx0 = fmaxf(mx0, __shfl_xor_sync(0xffffffffu, mx0, 1));
    mx0 = fmaxf(mx0, __shfl_xor_sync(0xffffffffu, mx0, 2));
    mx1 = fmaxf(mx1, __shfl_xor_sync(0xffffffffu, mx1, 1));
    mx1 = fmaxf(mx1, __shfl_xor_sync(0xffffffffu, mx1, 2));
    float s0 = 0.f, s1 = 0.f;
#pragma unroll
    for (int ni = 0; ni < 16; ni++) {
        float e;
        e = __expf(acc[ni][0] - mx0); acc[ni][0] = e; s0 += e;
        e = __expf(acc[ni][1] - mx0); acc[ni][1] = e; s0 += e;
        e = __expf(acc[ni][2] - mx1); acc[ni][2] = e; s1 += e;
        e = __expf(acc[ni][3] - mx1); acc[ni][3] = e; s1 += e;
    }
    s0 += __shfl_xor_sync(0xffffffffu, s0, 1);
    s0 += __shfl_xor_sync(0xffffffffu, s0, 2);
    s1 += __shfl_xor_sync(0xffffffffu, s1, 1);
    s1 += __shfl_xor_sync(0xffffffffu, s1, 2);
    const float inv0 = 1.f / s0, inv1 = 1.f / s1;

    // pack probs into fp16 hi/lo A-fragments
    uint32_t aph[8][4], apl[8][4];
#pragma unroll
    for (int kb = 0; kb < 8; kb++) {
        const int n0 = 2 * kb, n1 = n0 + 1;
        float p[8];
        p[0] = acc[n0][0] * inv0; p[1] = acc[n0][1] * inv0;
        p[2] = acc[n0][2] * inv1; p[3] = acc[n0][3] * inv1;
        p[4] = acc[n1][0] * inv0; p[5] = acc[n1][1] * inv0;
        p[6] = acc[n1][2] * inv1; p[7] = acc[n1][3] * inv1;
#pragma unroll
        for (int u = 0; u < 4; u++) {
            float a = p[2 * u], b = p[2 * u + 1];
            __half ha = __float2half_rn(a), hb = __float2half_rn(b);
            __half2 hh; hh.x = ha; hh.y = hb;
            aph[kb][u] = *reinterpret_cast<uint32_t*>(&hh);
            apl[kb][u] = pack_h16x2(a - __half2float(ha), b - __half2float(hb));
        }
    }

    float acco[8][4];
#pragma unroll
    for (int i = 0; i < 8; i++)
#pragma unroll
        for (int u = 0; u < 4; u++) acco[i][u] = 0.f;

#pragma unroll
    for (int kb = 0; kb < 8; kb++) {
        const int jrow = kb * 16 + ((lane >> 3) & 1) * 8 + (lane & 7);
        uint32_t vb[4][4];
#pragma unroll
        for (int nfp = 0; nfp < 4; nfp++) {
            const int ncol = nfp * 16 + (lane >> 4) * 8;
            LDMATRIX_X4_T(vb[nfp][0], vb[nfp][1], vb[nfp][2], vb[nfp][3],
                          sVh + jrow * 128 + ((((ncol >> 3) ^ (jrow & 7))) << 4));
        }
#pragma unroll
        for (int nfp = 0; nfp < 4; nfp++) {
            MMA_F16(acco[2 * nfp],     aph[kb][0], aph[kb][1], aph[kb][2], aph[kb][3], vb[nfp][0], vb[nfp][1]);
            MMA_F16(acco[2 * nfp + 1], aph[kb][0], aph[kb][1], aph[kb][2], aph[kb][3], vb[nfp][2], vb[nfp][3]);
        }
#pragma unroll
        for (int nfp = 0; nfp < 4; nfp++) {
            MMA_F16(acco[2 * nfp],     apl[kb][0], apl[kb][1], apl[kb][2], apl[kb][3], vb[nfp][0], vb[nfp][1]);
            MMA_F16(acco[2 * nfp + 1], apl[kb][0], apl[kb][1], apl[kb][2], apl[kb][3], vb[nfp][2], vb[nfp][3]);
        }
    }

    const int r0 = i0w + (lane >> 2), r1 = r0 + 8;
#pragma unroll
    for (int nf = 0; nf < 8; nf++) {
        const int c = H * 64 + nf * 8 + (lane & 3) * 2;
        const size_t t0 = (size_t)(r0 * 256 + cw) * OLD + c;
        const size_t t1 = (size_t)(r1 * 256 + cw) * OLD + c;
        split2_store_f16(g_Ohi + t0, g_Olo + t0, acco[nf][0], acco[nf][1]);
        split2_store_f16(g_Ohi + t1, g_Olo + t1, acco[nf][2], acco[nf][3]);
    }
}

// ---------------------------------------------------------------------------
// Tied row attention dots: fp16 2-term, split-K over r (DSPLIT=8).
// A = hq hi/lo (16KB), B = hk hi (8KB used of 16KB slot).
// ---------------------------------------------------------------------------
#define DOTS_SMEM (3 * 32768)

__global__ __launch_bounds__(256, 2) void dots_h_mma()
{
    extern __shared__ char smem[];
    const uint32_t sb = smem_to_u32(smem);
    const int tid = threadIdx.x, lane = tid & 31, wid = tid >> 5;
    const int wm = wid & 3, wn = wid >> 2;
    const int i0 = (blockIdx.x & 1) * 128, j0 = (blockIdx.x >> 1) * 128;
    const int H = blockIdx.y, sp = blockIdx.z;
    const int rbase = sp * (128 / DSPLIT);
    const int NC = (128 / DSPLIT) * 2;

    float acc[2][8][4];
#pragma unroll
    for (int i = 0; i < 2; i++)
#pragma unroll
        for (int j = 0; j < 8; j++)
#pragma unroll
            for (int u = 0; u < 4; u++) acc[i][j][u] = 0.f;

    auto load_chunk = [&](int c, int s) {
        const int r = rbase + (c >> 1), dhc = (c & 1) * 32;
        const size_t abase = ((size_t)(r * 256 + i0)) * PLD + 1536 + H * 64 + dhc;
        const size_t bbase = ((size_t)(r * 256 + j0)) * PLD + 2048 + H * 64 + dhc;
        const uint32_t sA = sb + s * 32768, sB = sA + 16384;
#pragma unroll
        for (int i = 0; i < 4; i++) {
            const int id = tid + i * 256;
            const int row = id & 127, g = id >> 7;
            const uint32_t off = row * 128 + ((g ^ (row & 7)) << 4);
            const __half* src = (g < 4) ? g_Ph : g_Pl;
            CP_ASYNC16(sA + off, src + abase + (size_t)row * PLD + (g & 3) * 8);
        }
#pragma unroll
        for (int i = 0; i < 2; i++) {
            const int id = tid + i * 256;
            const int row = id & 127, g = id >> 7;   // 0..3
            const uint32_t off = row * 128 + ((g ^ (row & 7)) << 4);
            CP_ASYNC16(sB + off, g_Ph + bbase + (size_t)row * PLD + g * 8);
        }
        CP_COMMIT();
    };

    load_chunk(0, 0);
    load_chunk(1, 1);
    for (int c = 0; c < NC; c++) {
        if (c < NC - 1) { CP_WAIT1(); } else { CP_WAIT0(); }
        __syncthreads();
        if (c + 2 < NC) load_chunk(c + 2, (c + 2) % 3);
        const uint32_t sA = sb + (c % 3) * 32768, sB = sA + 16384;
#pragma unroll
        for (int kb = 0; kb < 2; kb++) {
            const int lg = kb * 2 + (lane >> 4);
            uint32_t ah[2][4], al[2][4];
#pragma unroll
            for (int mi = 0; mi < 2; mi++) {
                const int row = wm * 32 + mi * 16 + (lane & 15);
                LDMATRIX_X4(ah[mi][0], ah[mi][1], ah[mi][2], ah[mi][3],
                            sA + row * 128 + (((lg) ^ (row & 7)) << 4));
                LDMATRIX_X4(al[mi][0], al[mi][1], al[mi][2], al[mi][3],
                            sA + row * 128 + (((lg + 4) ^ (row & 7)) << 4));
            }
            uint32_t b[4][4];
#pragma unroll
            for (int nf = 0; nf < 4; nf++) {
                const int row = wn * 64 + nf * 16 + (lane & 15);
                LDMATRIX_X4(b[nf][0], b[nf][1], b[nf][2], b[nf][3],
                            sB + row * 128 + (((lg) ^ (row & 7)) << 4));
            }
#pragma unroll
            for (int nf = 0; nf < 4; nf++)
#pragma unroll
                for (int mi = 0; mi < 2; mi++) {
                    MMA_F16(acc[mi][2 * nf],     ah[mi][0], ah[mi][1], ah[mi][2], ah[mi][3], b[nf][0], b[nf][2]);
                    MMA_F16(acc[mi][2 * nf + 1], ah[mi][0], ah[mi][1], ah[mi][2], ah[mi][3], b[nf][1], b[nf][3]);
                }
#pragma unroll
            for (int nf = 0; nf < 4; nf++)
#pragma unroll
                for (int mi = 0; mi < 2; mi++) {
                    MMA_F16(acc[mi][2 * nf],     al[mi][0], al[mi][1], al[mi][2], al[mi][3], b[nf][0], b[nf][2]);
                    MMA_F16(acc[mi][2 * nf + 1], al[mi][0], al[mi][1], al[mi][2], al[mi][3], b[nf][1], b[nf][3]);
                }
        }
    }

    float* Cp = g_Shp + (size_t)sp * 524288 + (size_t)H * 65536;
    const int qrow = lane >> 2, qcol2 = (lane & 3) * 2;
#pragma unroll
    for (int nj = 0; nj < 8; nj++) {
        const int n = j0 + wn * 64 + nj * 8 + qcol2;
#pragma unroll
        for (int mi = 0; mi < 2; mi++) {
            const int m = i0 + wm * 32 + mi * 16 + qrow;
            float2 v0, v1;
            v0.x = acc[mi][nj][0]; v0.y = acc[mi][nj][1];
            v1.x = acc[mi][nj][2]; v1.y = acc[mi][nj][3];
            *(float2*)(Cp + m * 256 + n) = v0;
            *(float2*)(Cp + (m + 8) * 256 + n) = v1;
        }
    }
}

// Sum DSPLIT partials, scale, softmax over 256, emit fp16 hi/lo probs.
__global__ __launch_bounds__(256) void softmax_h_kernel()
{
    const size_t base = (size_t)blockIdx.x * 256;
    const int t = threadIdx.x;
    __shared__ float red[256];
    float v = 0.f;
#pragma unroll
    for (int sp = 0; sp < DSPLIT; sp++)
        v += g_Shp[(size_t)sp * 524288 + base + t];
    v *= TSC;
    red[t] = v;
    __syncthreads();
#pragma unroll
    for (int s = 128; s > 0; s >>= 1) {
        if (t < s) red[t] = fmaxf(red[t], red[t + s]);
        __syncthreads();
    }
    const float m = red[0];
    __syncthreads();
    const float e = __expf(v - m);
    red[t] = e;
    __syncthreads();
#pragma unroll
    for (int s = 128; s > 0; s >>= 1) {
        if (t < s) red[t] += red[t + s];
        __syncthreads();
    }
    const float p = e / red[0];
    const __half h = __float2half_rn(p);
    g_Shh[base + t] = h;
    g_Shl[base + t] = __float2half_rn(p - __half2float(h));
}

// ---------------------------------------------------------------------------
// Tied row attention AV: fp16 2-term. A = probs hi/lo (32KB), V = hi (4KB).
// ---------------------------------------------------------------------------
#define AV_SMEM (2 * 36864)   // 72 KB

__global__ __launch_bounds__(256, 2) void av_h_mma()
{
    extern __shared__ char smem[];
    const uint32_t sb = smem_to_u32(smem);
    const int r = blockIdx.x, H = blockIdx.y;
    const int tid = threadIdx.x, lane = tid & 31, wid = tid >> 5;
    const int i0w = wid * 32;
    const int NC = 8;

    float acc[2][8][4];
#pragma unroll
    for (int i = 0; i < 2; i++)
#pragma unroll
        for (int j = 0; j < 8; j++)
#pragma unroll
            for (int u = 0; u < 4; u++) acc[i][j][u] = 0.f;

    auto load_chunk = [&](int c, int s) {
        const int jc = c << 5;
        const uint32_t sA = sb + s * 36864, sV = sA + 32768;
#pragma unroll
        for (int i = 0; i < 8; i++) {
            const int id = tid + i * 256;
            const int row = id & 255, g = id >> 8;
            const __half* src = (g < 4) ? g_Shh : g_Shl;
            CP_ASYNC16(sA + row * 128 + ((g ^ (row & 7)) << 4),
                       src + (size_t)H * 65536 + row * 256 + jc + (g & 3) * 8);
        }
        {
            const int id = tid;                       // 256 slots: 32 rows x 8 granules
            const int jrow = id & 31, g = (id >> 5) & 7;
            CP_ASYNC16(sV + jrow * 128 + ((g ^ (jrow & 7)) << 4),
                       g_Ph + (size_t)(r * 256 + jc + jrow) * PLD + 2560 + H * 64 + g * 8);
        }
        CP_COMMIT();
    };

    load_chunk(0, 0);
    load_chunk(1, 1);
    for (int c = 0; c < NC; c++) {
        if (c + 1 < NC) { CP_WAIT1(); } else { CP_WAIT0(); }
        __syncthreads();
        const uint32_t sA = sb + (c & 1) * 36864, sV = sA + 32768;
#pragma unroll
        for (int kb = 0; kb < 2; kb++) {
            const int lg = kb * 2 + (lane >> 4);
            uint32_t ah[2][4], al[2][4];
#pragma unroll
            for (int mi = 0; mi < 2; mi++) {
                const int row = i0w + mi * 16 + (lane & 15);
                LDMATRIX_X4(ah[mi][0], ah[mi][1], ah[mi][2], ah[mi][3],
                            sA + row * 128 + ((lg ^ (row & 7)) << 4));
                LDMATRIX_X4(al[mi][0], al[mi][1], al[mi][2], al[mi][3],
                            sA + row * 128 + (((lg + 4) ^ (row & 7)) << 4));
            }
            const int jrow = kb * 16 + ((lane >> 3) & 1) * 8 + (lane & 7);
            uint32_t vb[4][4];
#pragma unroll
            for (int nfp = 0; nfp < 4; nfp++) {
                const int ncol = nfp * 16 + (lane >> 4) * 8;
                LDMATRIX_X4_T(vb[nfp][0], vb[nfp][1], vb[nfp][2], vb[nfp][3],
                              sV + jrow * 128 + ((((ncol >> 3) ^ (jrow & 7))) << 4));
            }
#pragma unroll
            for (int nfp = 0; nfp < 4; nfp++)
#pragma unroll
                for (int mi = 0; mi < 2; mi++) {
                    MMA_F16(acc[mi][2 * nfp],     ah[mi][0], ah[mi][1], ah[mi][2], ah[mi][3], vb[nfp][0], vb[nfp][1]);
                    MMA_F16(acc[mi][2 * nfp + 1], ah[mi][0], ah[mi][1], ah[mi][2], ah[mi][3], vb[nfp][2], vb[nfp][3]);
                }
#pragma unroll
            for (int nfp = 0; nfp < 4; nfp++)
#pragma unroll
                for (int mi = 0; mi < 2; mi++) {
                    MMA_F16(acc[mi][2 * nfp],     al[mi][0], al[mi][1], al[mi][2], al[mi][3], vb[nfp][0], vb[nfp][1]);
                    MMA_F16(acc[mi][2 * nfp + 1], al[mi][0], al[mi][1], al[mi][2], al[mi][3], vb[nfp][2], vb[nfp][3]);
                }
        }
        __syncthreads();
        if (c + 2 < NC) load_chunk(c + 2, c & 1);
    }

    const int qrow = lane >> 2, qcol2 = (lane & 3) * 2;
#pragma unroll
    for (int nf = 0; nf < 8; nf++) {
        const int c = 512 + H * 64 + nf * 8 + qcol2;
#pragma unroll
        for (int mi = 0; mi < 2; mi++) {
            const int i = i0w + mi * 16 + qrow;
            const size_t t0 = (size_t)(r * 256 + i) * OLD + c;
            const size_t t1 = (size_t)(r * 256 + i + 8) * OLD + c;
            split2_store_f16(g_Ohi + t0, g_Olo + t0, acc[mi][nf][0], acc[mi][nf][1]);
            split2_store_f16(g_Ohi + t1, g_Olo + t1, acc[mi][nf][2], acc[mi][nf][3]);
        }
    }
}

// ---------------------------------------------------------------------------
extern "C" void kernel_launch(void* const* d_in, const int* in_sizes, int n_in,
                              void* d_out, int out_size)
{
    const float* x      = (const float*)d_in[0];
    const float* wq_w   = (const float*)d_in[1];
    const float* wkv_w  = (const float*)d_in[2];
    const float* wout_w = (const float*)d_in[3];
    const float* wout_b = (const float*)d_in[4];
    const float* hq_w   = (const float*)d_in[5];
    const float* hkv_w  = (const float*)d_in[6];
    const float* hout_w = (const float*)d_in[7];
    const float* hout_b = (const float*)d_in[8];
    float* out = (float*)d_out;

    __half *x16h, *x16l, *Bp16, *Ph, *Pl, *Ohi, *Olo, *Bo16;
    cudaGetSymbolAddress((void**)&x16h, g_x16h);
    cudaGetSymbolAddress((void**)&x16l, g_x16l);
    cudaGetSymbolAddress((void**)&Bp16, g_Bp16);
    cudaGetSymbolAddress((void**)&Ph, g_Ph);
    cudaGetSymbolAddress((void**)&Pl, g_Pl);
    cudaGetSymbolAddress((void**)&Ohi, g_Ohi);
    cudaGetSymbolAddress((void**)&Olo, g_Olo);
    cudaGetSymbolAddress((void**)&Bo16, g_Bo16);

    cudaFuncSetAttribute(gemm_f16, cudaFuncAttributeMaxDynamicSharedMemorySize, GEMM_SMEM);
    cudaFuncSetAttribute(attn_w_mma, cudaFuncAttributeMaxDynamicSharedMemorySize, ATTNW_SMEM);
    cudaFuncSetAttribute(dots_h_mma, cudaFuncAttributeMaxDynamicSharedMemorySize, DOTS_SMEM);
    cudaFuncSetAttribute(av_h_mma, cudaFuncAttributeMaxDynamicSharedMemorySize, AV_SMEM);

    // 1) splits + weight panels
    split_f16_kernel<<<4096, 256>>>(x, x16h, x16l, (size_t)NTOK * DIMD);
    build_Bp_kernel<<<3072, 256>>>(wq_w, wkv_w, hq_w, hkv_w);
    build_Bo_kernel<<<1024, 256>>>(wout_w, hout_w);

    // 2) projections -> P (fp16 hi/lo)
    gemm_f16<<<dim3(24, 256), 256, GEMM_SMEM>>>(x16h, x16l, DIMD, Bp16, DIMD,
                                                nullptr, Ph, Pl, PLD, DIMD,
                                                nullptr, nullptr);

    // 3) column attention (w branch) -> O cols [0,512)
    attn_w_mma<<<dim3(256, 8), 256, ATTNW_SMEM>>>();

    // 4) tied row attention (h branch) -> O cols [512,1024)
    dots_h_mma<<<dim3(4, 8, DSPLIT), 256, DOTS_SMEM>>>();
    softmax_h_kernel<<<2048, 256>>>();
    av_h_mma<<<dim3(128, 8), 256, AV_SMEM>>>();

    // 5) out = O @ [wout;hout] + biases (fp16 2-term)
    gemm_f16<<<dim3(2, 256), 256, GEMM_SMEM>>>(Ohi, Olo, OLD, Bo16, 1024,
                                               out, nullptr, nullptr, DIMD, 1024,
                                               wout_b, hout_b);
}